// round 12
// baseline (speedup 1.0000x reference)
#include <cuda_runtime.h>
#include <math.h>

#define B    8
#define HD   768
#define HD4  192
#define LP   512
#define LL   256
#define CBN  4096
#define NS   9
#define TT   4

#define OFF_SUM 0
#define OFF_SL  24576
#define OFF_SP  24608
#define OFF_OP  24640
#define OFF_CL  155712

// ---------------- device scratch ----------------
__device__ __align__(16) float g_cat[B * 2 * HD];
__device__ __align__(16) float g_stateA[B * HD];
__device__ __align__(16) float g_stateB[B * HD];
__device__ __align__(16) float g_sq[B * HD];
__device__ __align__(16) float g_qprime[B * HD];
__device__ __align__(16) float g_unum[B * HD];
__device__ float g_Dnum[B];
__device__ __align__(16) float g_ctx[B * HD];
__device__ __align__(16) float g_oppre[B * HD];
__device__ __align__(16) float g_sq2[B * HD];
__device__ __align__(16) float g_qk2[B * HD];
__device__ __align__(16) float g_sqs[NS * HD];
__device__ __align__(16) float g_sqk2[NS * HD];
__device__ float g_gq[NS];
__device__ float g_glog[B];
__device__ __align__(16) float g_snum[B * NS * HD];   // Σ exp·prompt per slot
__device__ float g_sden[B * NS];                      // Σ exp per slot
__device__ __align__(16) float g_ssum[B * HD];
__device__ __align__(16) float g_gi[B * 3 * HD];
__device__ __align__(16) float g_gh[B * 3 * HD];
__device__ float g_stoplog[B];
__device__ unsigned long long g_amin[B];

// ---------------- helpers ----------------

#define FMA4(ACC, A, Bv) \
    ACC.x = fmaf(A, Bv.x, ACC.x); ACC.y = fmaf(A, Bv.y, ACC.y); \
    ACC.z = fmaf(A, Bv.z, ACC.z); ACC.w = fmaf(A, Bv.w, ACC.w);

template <int M>
__device__ __forceinline__ void colgemv4(const float* __restrict__ X, int ldx,
                                         const float* __restrict__ W,
                                         float* __restrict__ Y,
                                         int K, int nks, int cid, float* SM) {
    int kr = K / nks, k0 = cid * kr;
    for (int i = threadIdx.x; i < M * kr; i += 256) {
        int m = i / kr, kk = i - m * kr;
        SM[i] = X[(size_t)m * ldx + k0 + kk];
    }
    __syncthreads();
    if (threadIdx.x < HD4) {
        const float4* W4 = reinterpret_cast<const float4*>(W);
        float4 acc[M];
#pragma unroll
        for (int m = 0; m < M; m++) acc[m] = make_float4(0.f, 0.f, 0.f, 0.f);
#pragma unroll 4
        for (int kk = 0; kk < kr; kk++) {
            float4 wv = W4[(size_t)(k0 + kk) * HD4 + threadIdx.x];
#pragma unroll
            for (int m = 0; m < M; m++) {
                float s = SM[m * kr + kk];
                FMA4(acc[m], s, wv);
            }
        }
        int j = threadIdx.x * 4;
#pragma unroll
        for (int m = 0; m < M; m++) {
            atomicAdd(&Y[(size_t)m * HD + j],     acc[m].x);
            atomicAdd(&Y[(size_t)m * HD + j + 1], acc[m].y);
            atomicAdd(&Y[(size_t)m * HD + j + 2], acc[m].z);
            atomicAdd(&Y[(size_t)m * HD + j + 3], acc[m].w);
        }
    }
}

template <int M>
__device__ __forceinline__ void rowdot(const float* __restrict__ W,
                                       const float* __restrict__ Xg,
                                       float* __restrict__ Y,
                                       int cid, int nc, float* SM) {
    int tid = threadIdx.x, w = tid >> 5, lane = tid & 31;
    for (int i = tid; i < M * HD; i += 256) SM[i] = Xg[i];
    __syncthreads();
    const float4* SM4 = reinterpret_cast<const float4*>(SM);
    for (int n = cid * 8 + w; n < HD; n += nc * 8) {
        const float4* wr = reinterpret_cast<const float4*>(W + (size_t)n * HD);
        float acc[M];
#pragma unroll
        for (int m = 0; m < M; m++) acc[m] = 0.f;
#pragma unroll
        for (int k = lane; k < HD4; k += 32) {
            float4 wv = wr[k];
#pragma unroll
            for (int m = 0; m < M; m++) {
                float4 s = SM4[m * HD4 + k];
                acc[m] = fmaf(wv.x, s.x, acc[m]);
                acc[m] = fmaf(wv.y, s.y, acc[m]);
                acc[m] = fmaf(wv.z, s.z, acc[m]);
                acc[m] = fmaf(wv.w, s.w, acc[m]);
            }
        }
#pragma unroll
        for (int m = 0; m < M; m++) {
#pragma unroll
            for (int off = 16; off; off >>= 1)
                acc[m] += __shfl_down_sync(0xffffffffu, acc[m], off);
        }
        if (lane == 0) {
#pragma unroll
            for (int m = 0; m < M; m++) Y[(size_t)m * HD + n] = acc[m];
        }
    }
}

// body only: SM must already hold M*HD staged values (synced)
template <int M>
__device__ __forceinline__ void rowdot4_body(const float* __restrict__ W,
                                             float* __restrict__ Y,
                                             int ldy, int Ntot,
                                             int cid, int nc, const float* SM) {
    int tid = threadIdx.x, w = tid >> 5, lane = tid & 31;
    const float4* SM4 = reinterpret_cast<const float4*>(SM);
    int stride = nc * 8;
    for (int n = cid * 8 + w; n < Ntot; n += 4 * stride) {
        int n1 = n + stride, n2 = n + 2 * stride, n3 = n + 3 * stride;
        bool q1 = n1 < Ntot, q2 = n2 < Ntot, q3 = n3 < Ntot;
        const float4* w0 = reinterpret_cast<const float4*>(W + (size_t)n * HD);
        const float4* w1 = reinterpret_cast<const float4*>(W + (size_t)(q1 ? n1 : n) * HD);
        const float4* w2 = reinterpret_cast<const float4*>(W + (size_t)(q2 ? n2 : n) * HD);
        const float4* w3 = reinterpret_cast<const float4*>(W + (size_t)(q3 ? n3 : n) * HD);
        float a0[M], a1[M], a2[M], a3[M];
#pragma unroll
        for (int m = 0; m < M; m++) { a0[m] = 0.f; a1[m] = 0.f; a2[m] = 0.f; a3[m] = 0.f; }
#pragma unroll 2
        for (int k = lane; k < HD4; k += 32) {
            float4 x0 = w0[k], x1 = w1[k], x2 = w2[k], x3 = w3[k];
#pragma unroll
            for (int m = 0; m < M; m++) {
                float4 s = SM4[m * HD4 + k];
                a0[m] = fmaf(x0.x, s.x, a0[m]); a0[m] = fmaf(x0.y, s.y, a0[m]);
                a0[m] = fmaf(x0.z, s.z, a0[m]); a0[m] = fmaf(x0.w, s.w, a0[m]);
                a1[m] = fmaf(x1.x, s.x, a1[m]); a1[m] = fmaf(x1.y, s.y, a1[m]);
                a1[m] = fmaf(x1.z, s.z, a1[m]); a1[m] = fmaf(x1.w, s.w, a1[m]);
                a2[m] = fmaf(x2.x, s.x, a2[m]); a2[m] = fmaf(x2.y, s.y, a2[m]);
                a2[m] = fmaf(x2.z, s.z, a2[m]); a2[m] = fmaf(x2.w, s.w, a2[m]);
                a3[m] = fmaf(x3.x, s.x, a3[m]); a3[m] = fmaf(x3.y, s.y, a3[m]);
                a3[m] = fmaf(x3.z, s.z, a3[m]); a3[m] = fmaf(x3.w, s.w, a3[m]);
            }
        }
#pragma unroll
        for (int m = 0; m < M; m++) {
            float v0 = a0[m], v1 = a1[m], v2 = a2[m], v3 = a3[m];
#pragma unroll
            for (int off = 16; off; off >>= 1) {
                v0 += __shfl_down_sync(0xffffffffu, v0, off);
                v1 += __shfl_down_sync(0xffffffffu, v1, off);
                v2 += __shfl_down_sync(0xffffffffu, v2, off);
                v3 += __shfl_down_sync(0xffffffffu, v3, off);
            }
            if (lane == 0) {
                Y[(size_t)m * ldy + n] = v0;
                if (q1) Y[(size_t)m * ldy + n1] = v1;
                if (q2) Y[(size_t)m * ldy + n2] = v2;
                if (q3) Y[(size_t)m * ldy + n3] = v3;
            }
        }
    }
}

template <int M>
__device__ __forceinline__ void rowdot4(const float* __restrict__ W,
                                        const float* __restrict__ Xg,
                                        float* __restrict__ Y,
                                        int ldy, int Ntot,
                                        int cid, int nc, float* SM) {
    for (int i = threadIdx.x; i < M * HD; i += 256) SM[i] = Xg[i];
    __syncthreads();
    rowdot4_body<M>(W, Y, ldy, Ntot, cid, nc, SM);
}

// ---------------- kernels ----------------

__global__ void k_reset() {
    int gid = blockIdx.x * 256 + threadIdx.x;
    const int stride = 32 * 256;
    for (int i = gid; i < B * HD; i += stride) {
        g_sq[i] = 0.f; g_unum[i] = 0.f; g_ctx[i] = 0.f; g_oppre[i] = 0.f;
        g_sq2[i] = 0.f; g_ssum[i] = 0.f;
    }
    for (int i = gid; i < B * NS * HD; i += stride) g_snum[i] = 0.f;
    for (int i = gid; i < NS * HD; i += stride) g_sqs[i] = 0.f;
    if (gid < B * NS) g_sden[gid] = 0.f;
    if (gid < B) { g_amin[gid] = 0xFFFFFFFFFFFFFFFFull; g_stoplog[gid] = 0.f; g_Dnum[gid] = 0.f; }
}

__global__ void k_pp1(const float* __restrict__ prompt, const float* __restrict__ logic) {
    int w = threadIdx.x >> 5, lane = threadIdx.x & 31;
    int wt = blockIdx.x * 8 + w;
    if (wt < 48) {
        int b = wt / 6, hc = wt % 6;
        int h4 = hc * 32 + lane;
        const float4* p = reinterpret_cast<const float4*>(prompt + (size_t)b * LP * HD);
        float4 s = make_float4(0.f, 0.f, 0.f, 0.f);
#pragma unroll 8
        for (int l = 0; l < LP; l++) {
            float4 v = p[(size_t)l * HD4 + h4];
            s.x += v.x; s.y += v.y; s.z += v.z; s.w += v.w;
        }
        int h = h4 * 4;
        float inv = 1.f / (float)LP;
        g_cat[b * 2 * HD + h]     = s.x * inv;
        g_cat[b * 2 * HD + h + 1] = s.y * inv;
        g_cat[b * 2 * HD + h + 2] = s.z * inv;
        g_cat[b * 2 * HD + h + 3] = s.w * inv;
    } else {
        int t2 = wt - 48;
        int b = t2 / 6, hc = t2 % 6;
        int h4 = hc * 32 + lane;
        const float4* p = reinterpret_cast<const float4*>(logic + (size_t)b * LL * HD);
        float4 s = make_float4(0.f, 0.f, 0.f, 0.f);
#pragma unroll 8
        for (int l = 0; l < LL; l++) {
            float4 v = p[(size_t)l * HD4 + h4];
            s.x += v.x; s.y += v.y; s.z += v.z; s.w += v.w;
        }
        int h = h4 * 4;
        float inv = 1.f / (float)LL;
        g_cat[b * 2 * HD + HD + h]     = s.x * inv;
        g_cat[b * 2 * HD + HD + h + 1] = s.y * inv;
        g_cat[b * 2 * HD + HD + h + 2] = s.z * inv;
        g_cat[b * 2 * HD + HD + h + 3] = s.w * inv;
    }
}

__global__ void k_pp2(const float* __restrict__ w_init, const float* __restrict__ slot_q,
                      const float* __restrict__ w_slot_q, const float* __restrict__ w_gate) {
    __shared__ __align__(16) float SM[9 * 48];
    int cid = blockIdx.x, w = threadIdx.x >> 5, lane = threadIdx.x & 31;
    if (cid < 32) {
        colgemv4<8>(g_cat, 2 * HD, w_init, g_sq, 2 * HD, 32, cid, SM);
    } else if (cid < 48) {
        colgemv4<9>(slot_q, HD, w_slot_q, g_sqs, HD, 16, cid - 32, SM);
    } else {
        for (int s = w; s < NS; s += 8) {
            float p = 0.f;
            for (int k = lane; k < HD; k += 32)
                p = fmaf(slot_q[s * HD + k], w_gate[k], p);
#pragma unroll
            for (int off = 16; off; off >>= 1) p += __shfl_down_sync(0xffffffffu, p, off);
            if (lane == 0) g_gq[s] = p;
        }
    }
}

__global__ void k_pp3(const float* __restrict__ w_k) {
    __shared__ __align__(16) float SM[NS * HD];
    int cid = blockIdx.x, tid = threadIdx.x;
    if (cid < 8) {
        int b = cid;
        for (int rep = 0; rep < 3; rep++) {
            int j = rep * 256 + tid;
            g_stateA[b * HD + j] = tanhf(g_sq[b * HD + j]);
            g_sq[b * HD + j] = 0.f;
        }
    } else {
        rowdot<9>(w_k, g_sqs, g_sqk2, cid - 8, 140, SM);
    }
}

// grid 106: sq += state@w_q (32) + gh = w_hh@stOld (74)
__global__ void k_a(const float* __restrict__ st, const float* __restrict__ w_q,
                    const float* __restrict__ w_hh) {
    __shared__ __align__(16) float SM[B * HD];
    if (blockIdx.x < 32) colgemv4<8>(st, HD, w_q, g_sq, HD, 32, blockIdx.x, SM);
    else rowdot4<8>(w_hh, st, g_gh, 3 * HD, 3 * HD, blockIdx.x - 32, 74, SM);
}

// grid 96: qprime = w_k @ sq
__global__ void k_b(const float* __restrict__ w_k) {
    __shared__ __align__(16) float SM[8 * HD];
    rowdot<8>(w_k, g_sq, g_qprime, blockIdx.x, 96, SM);
}

// grid 88: fused state scores + exp + weighted prompt accum (64) + zero sq (24)
__global__ void k_cd(const float* __restrict__ prompt) {
    int cid = blockIdx.x, tid = threadIdx.x, w = tid >> 5, lane = tid & 31;
    const float scale = 0.03608439182435161f;
    if (cid < 64) {
        __shared__ __align__(16) float su[4 * HD];
        __shared__ float sD[8];
        int b = cid >> 3, ch = cid & 7;
        const float4* qp4 = reinterpret_cast<const float4*>(g_qprime + b * HD);
        float4 qv[6];
#pragma unroll
        for (int q = 0; q < 6; q++) qv[q] = qp4[q * 32 + lane];
        float4 acc[6];
#pragma unroll
        for (int q = 0; q < 6; q++) acc[q] = make_float4(0.f, 0.f, 0.f, 0.f);
        float Dw = 0.f;
        const float4* pr = reinterpret_cast<const float4*>(
            prompt + ((size_t)(b * LP + ch * 64)) * HD);
        for (int r = 0; r < 8; r++) {
            int l = w * 8 + r;
            const float4* row = pr + (size_t)l * HD4;
            float4 pv[6];
#pragma unroll
            for (int q = 0; q < 6; q++) pv[q] = row[q * 32 + lane];
            float s = 0.f;
#pragma unroll
            for (int q = 0; q < 6; q++) {
                s = fmaf(pv[q].x, qv[q].x, s); s = fmaf(pv[q].y, qv[q].y, s);
                s = fmaf(pv[q].z, qv[q].z, s); s = fmaf(pv[q].w, qv[q].w, s);
            }
#pragma unroll
            for (int off = 16; off; off >>= 1) s += __shfl_xor_sync(0xffffffffu, s, off);
            float e = expf(s * scale);
            Dw += e;
#pragma unroll
            for (int q = 0; q < 6; q++) { FMA4(acc[q], e, pv[q]); }
        }
        float4* su4 = reinterpret_cast<float4*>(su);
        if (w < 4) {
#pragma unroll
            for (int q = 0; q < 6; q++) su4[w * HD4 + q * 32 + lane] = acc[q];
        }
        if (lane == 0) sD[w] = Dw;
        __syncthreads();
        if (w >= 4) {
#pragma unroll
            for (int q = 0; q < 6; q++) {
                float4 t = su4[(w - 4) * HD4 + q * 32 + lane];
                t.x += acc[q].x; t.y += acc[q].y; t.z += acc[q].z; t.w += acc[q].w;
                su4[(w - 4) * HD4 + q * 32 + lane] = t;
            }
        }
        __syncthreads();
        for (int r = 0; r < 3; r++) {
            int j = r * 256 + tid;
            float v = su[j] + su[HD + j] + su[2 * HD + j] + su[3 * HD + j];
            atomicAdd(&g_unum[b * HD + j], v);
        }
        if (tid == 0) {
            float d = sD[0] + sD[1] + sD[2] + sD[3] + sD[4] + sD[5] + sD[6] + sD[7];
            atomicAdd(&g_Dnum[b], d);
        }
    } else {
        int i = (cid - 64) * 256 + tid;
        g_sq[i] = 0.f;
    }
}

// grid 33: ctx += (unum/D) @ w_v (32) + reset amin (1)
__global__ void k_e(const float* __restrict__ w_v) {
    __shared__ __align__(16) float SM[8 * 24];
    if (blockIdx.x < 32) {
        int cid = blockIdx.x;
        int kr = 24, k0 = cid * kr;
        for (int i = threadIdx.x; i < 8 * kr; i += 256) {
            int m = i / kr, kk = i - m * kr;
            SM[i] = g_unum[m * HD + k0 + kk] / g_Dnum[m];
        }
        __syncthreads();
        if (threadIdx.x < HD4) {
            const float4* W4 = reinterpret_cast<const float4*>(w_v);
            float4 acc[8];
#pragma unroll
            for (int m = 0; m < 8; m++) acc[m] = make_float4(0.f, 0.f, 0.f, 0.f);
#pragma unroll 4
            for (int kk = 0; kk < 24; kk++) {
                float4 wv = W4[(size_t)(k0 + kk) * HD4 + threadIdx.x];
#pragma unroll
                for (int m = 0; m < 8; m++) {
                    float s = SM[m * 24 + kk];
                    FMA4(acc[m], s, wv);
                }
            }
            int j = threadIdx.x * 4;
#pragma unroll
            for (int m = 0; m < 8; m++) {
                atomicAdd(&g_ctx[(size_t)m * HD + j],     acc[m].x);
                atomicAdd(&g_ctx[(size_t)m * HD + j + 1], acc[m].y);
                atomicAdd(&g_ctx[(size_t)m * HD + j + 2], acc[m].z);
                atomicAdd(&g_ctx[(size_t)m * HD + j + 3], acc[m].w);
            }
        }
    } else if (threadIdx.x < B) g_amin[threadIdx.x] = 0xFFFFFFFFFFFFFFFFull;
}

// grid 90: oppre (32), sq2 (32), glog (1), stop1 (1), zero unum/Dnum (24)
__global__ void k_f(const float* __restrict__ w_op_pre, const float* __restrict__ w_slot_q,
                    const float* __restrict__ w_gate, const float* __restrict__ w_stop) {
    __shared__ __align__(16) float SM[8 * 24];
    int cid = blockIdx.x, w = threadIdx.x >> 5, lane = threadIdx.x & 31;
    if (cid < 32) colgemv4<8>(g_ctx, HD, w_op_pre, g_oppre, HD, 32, cid, SM);
    else if (cid < 64) colgemv4<8>(g_ctx, HD, w_slot_q, g_sq2, HD, 32, cid - 32, SM);
    else if (cid == 64) {
        int b = w;
        float p = 0.f;
        for (int k = lane; k < HD; k += 32) p = fmaf(g_ctx[b * HD + k], w_gate[k], p);
#pragma unroll
        for (int off = 16; off; off >>= 1) p += __shfl_down_sync(0xffffffffu, p, off);
        if (lane == 0) g_glog[b] = p;
    } else if (cid == 65) {
        int b = w;
        float p = 0.f;
        for (int k = lane; k < HD; k += 32) p = fmaf(g_ctx[b * HD + k], w_stop[k], p);
#pragma unroll
        for (int off = 16; off; off >>= 1) p += __shfl_down_sync(0xffffffffu, p, off);
        if (lane == 0) g_stoplog[b] = p;
    } else {
        int i = (cid - 66) * 256 + threadIdx.x;
        g_unum[i] = 0.f;
        if (cid == 66 && threadIdx.x < B) g_Dnum[threadIdx.x] = 0.f;
    }
}

// grid 148: codebook (118) + qk2 = w_k@sq2 (30)
__global__ void k_g(const float* __restrict__ cbk, const float* __restrict__ w_k,
                    float* __restrict__ out, int t) {
    __shared__ __align__(16) float SM[B * HD];
    int cid = blockIdx.x, tid = threadIdx.x, w = tid >> 5, lane = tid & 31;
    if (cid < 118) {
        for (int i = tid; i < B * HD; i += 256) SM[i] = g_oppre[i];
        __syncthreads();
        const float4* SM4 = reinterpret_cast<const float4*>(SM);
        for (int c0 = cid * 8 + w; c0 < CBN; c0 += 2 * 944) {
            int c1 = c0 + 944;
            bool q1 = c1 < CBN;
            const float4* r0 = reinterpret_cast<const float4*>(cbk + (size_t)c0 * HD);
            const float4* r1 = reinterpret_cast<const float4*>(cbk + (size_t)(q1 ? c1 : c0) * HD);
            float a0[B], a1[B];
#pragma unroll
            for (int m = 0; m < B; m++) { a0[m] = 0.f; a1[m] = 0.f; }
#pragma unroll 2
            for (int k = lane; k < HD4; k += 32) {
                float4 x0 = r0[k], x1 = r1[k];
#pragma unroll
                for (int m = 0; m < B; m++) {
                    float4 sv = SM4[m * HD4 + k];
                    float d;
                    d = sv.x - x0.x; a0[m] = fmaf(d, d, a0[m]);
                    d = sv.y - x0.y; a0[m] = fmaf(d, d, a0[m]);
                    d = sv.z - x0.z; a0[m] = fmaf(d, d, a0[m]);
                    d = sv.w - x0.w; a0[m] = fmaf(d, d, a0[m]);
                    d = sv.x - x1.x; a1[m] = fmaf(d, d, a1[m]);
                    d = sv.y - x1.y; a1[m] = fmaf(d, d, a1[m]);
                    d = sv.z - x1.z; a1[m] = fmaf(d, d, a1[m]);
                    d = sv.w - x1.w; a1[m] = fmaf(d, d, a1[m]);
                }
            }
#pragma unroll
            for (int m = 0; m < B; m++) {
                float v0 = a0[m], v1 = a1[m];
#pragma unroll
                for (int off = 16; off; off >>= 1) {
                    v0 += __shfl_down_sync(0xffffffffu, v0, off);
                    v1 += __shfl_down_sync(0xffffffffu, v1, off);
                }
                if (lane == 0) {
                    out[OFF_OP + ((size_t)m * TT + t) * CBN + c0] = -v0;
                    unsigned long long key0 =
                        ((unsigned long long)__float_as_uint(v0) << 32) | (unsigned)c0;
                    atomicMin(&g_amin[m], key0);
                    if (q1) {
                        out[OFF_OP + ((size_t)m * TT + t) * CBN + c1] = -v1;
                        unsigned long long key1 =
                            ((unsigned long long)__float_as_uint(v1) << 32) | (unsigned)c1;
                        atomicMin(&g_amin[m], key1);
                    }
                }
            }
        }
    } else {
        rowdot4<8>(w_k, g_sq2, g_qk2, HD, HD, cid - 118, 30, SM);
    }
}

// grid 88: fused slot scores + exp + per-slot weighted prompt accum (64)
//          + zero ctx/oppre/sq2 (24)
__global__ void k_hs(const float* __restrict__ prompt) {
    __shared__ __align__(16) float SQ[NS * HD];
    __shared__ float E[NS * 64];
    int cid = blockIdx.x, tid = threadIdx.x, w = tid >> 5, lane = tid & 31;
    const float scale = 0.03608439182435161f;
    if (cid < 64) {
        int b = cid >> 3, ch = cid & 7;
        for (int i = tid; i < NS * HD; i += 256) {
            int k = i % HD;
            SQ[i] = g_qk2[b * HD + k] + g_sqk2[i];
        }
        __syncthreads();
        const float4* SQ4 = reinterpret_cast<const float4*>(SQ);
        const float4* p0 = reinterpret_cast<const float4*>(
            prompt + ((size_t)(b * LP + ch * 64)) * HD);
        // phase 1: scores -> exp into E
#pragma unroll
        for (int g = 0; g < 2; g++) {
            int l0 = w * 8 + g * 4;
            const float4* pr = p0 + (size_t)l0 * HD4;
            float a0[NS], a1[NS], a2[NS], a3[NS];
#pragma unroll
            for (int s = 0; s < NS; s++) { a0[s] = 0.f; a1[s] = 0.f; a2[s] = 0.f; a3[s] = 0.f; }
#pragma unroll 2
            for (int k = lane; k < HD4; k += 32) {
                float4 v0 = pr[k], v1 = pr[HD4 + k], v2 = pr[2 * HD4 + k], v3 = pr[3 * HD4 + k];
#pragma unroll
                for (int s = 0; s < NS; s++) {
                    float4 q = SQ4[s * HD4 + k];
                    a0[s] = fmaf(v0.x, q.x, a0[s]); a0[s] = fmaf(v0.y, q.y, a0[s]);
                    a0[s] = fmaf(v0.z, q.z, a0[s]); a0[s] = fmaf(v0.w, q.w, a0[s]);
                    a1[s] = fmaf(v1.x, q.x, a1[s]); a1[s] = fmaf(v1.y, q.y, a1[s]);
                    a1[s] = fmaf(v1.z, q.z, a1[s]); a1[s] = fmaf(v1.w, q.w, a1[s]);
                    a2[s] = fmaf(v2.x, q.x, a2[s]); a2[s] = fmaf(v2.y, q.y, a2[s]);
                    a2[s] = fmaf(v2.z, q.z, a2[s]); a2[s] = fmaf(v2.w, q.w, a2[s]);
                    a3[s] = fmaf(v3.x, q.x, a3[s]); a3[s] = fmaf(v3.y, q.y, a3[s]);
                    a3[s] = fmaf(v3.z, q.z, a3[s]); a3[s] = fmaf(v3.w, q.w, a3[s]);
                }
            }
#pragma unroll
            for (int s = 0; s < NS; s++) {
                float v0 = a0[s], v1 = a1[s], v2 = a2[s], v3 = a3[s];
#pragma unroll
                for (int off = 16; off; off >>= 1) {
                    v0 += __shfl_down_sync(0xffffffffu, v0, off);
                    v1 += __shfl_down_sync(0xffffffffu, v1, off);
                    v2 += __shfl_down_sync(0xffffffffu, v2, off);
                    v3 += __shfl_down_sync(0xffffffffu, v3, off);
                }
                if (lane == 0) {
                    E[s * 64 + l0]     = expf(v0 * scale);
                    E[s * 64 + l0 + 1] = expf(v1 * scale);
                    E[s * 64 + l0 + 2] = expf(v2 * scale);
                    E[s * 64 + l0 + 3] = expf(v3 * scale);
                }
            }
        }
        __syncthreads();
        // denominators
        for (int s = w; s < NS; s += 8) {
            float p = E[s * 64 + lane] + E[s * 64 + lane + 32];
#pragma unroll
            for (int off = 16; off; off >>= 1) p += __shfl_down_sync(0xffffffffu, p, off);
            if (lane == 0) atomicAdd(&g_sden[b * NS + s], p);
        }
        // phase 2: per-slot weighted prompt accumulation (rows L1-hot)
        if (tid < HD4) {
            float4 acc[NS];
#pragma unroll
            for (int s = 0; s < NS; s++) acc[s] = make_float4(0.f, 0.f, 0.f, 0.f);
            for (int l = 0; l < 64; l++) {
                float4 pv = p0[(size_t)l * HD4 + tid];
#pragma unroll
                for (int s = 0; s < NS; s++) {
                    float e = E[s * 64 + l];
                    FMA4(acc[s], e, pv);
                }
            }
            int j = tid * 4;
#pragma unroll
            for (int s = 0; s < NS; s++) {
                float* dst = &g_snum[((size_t)(b * NS + s)) * HD + j];
                atomicAdd(&dst[0], acc[s].x);
                atomicAdd(&dst[1], acc[s].y);
                atomicAdd(&dst[2], acc[s].z);
                atomicAdd(&dst[3], acc[s].w);
            }
        }
    } else {
        for (int i = (cid - 64) * 256 + tid; i < 3 * B * HD; i += 24 * 256) {
            if (i < B * HD) g_ctx[i] = 0.f;
            else if (i < 2 * B * HD) g_oppre[i - B * HD] = 0.f;
            else g_sq2[i - 2 * B * HD] = 0.f;
        }
    }
}

// grid 32: ssum += (Σ_s coef·snum) @ w_v, collapse computed inline
__global__ void k_k2(const float* __restrict__ w_v, const float* __restrict__ b_gate) {
    __shared__ __align__(16) float SM[8 * 24];
    __shared__ float coef[B * NS];
    int cid = blockIdx.x, tid = threadIdx.x;
    float bg = b_gate[0];
    int myge = 0;
    if (tid < B * NS) {
        float lg = g_glog[tid / NS] + g_gq[tid % NS] + bg;
        myge = (lg >= 0.f) ? 1 : 0;
    }
    int any = __syncthreads_or(myge);
    if (tid < B) {
        int b = tid;
        float mask[NS], cnt = 0.f;
        if (any) {
            for (int s = 0; s < NS; s++) {
                float m = (g_glog[b] + g_gq[s] + bg >= 0.f) ? 1.f : 0.f;
                mask[s] = m; cnt += m;
            }
        } else {
            int arg = 0; float best = g_glog[b] + g_gq[0] + bg;
            for (int s = 1; s < NS; s++) {
                float v = g_glog[b] + g_gq[s] + bg;
                if (v > best) { best = v; arg = s; }
            }
            for (int s = 0; s < NS; s++) mask[s] = (s == arg) ? 1.f : 0.f;
            cnt = 1.f;
        }
        float invcnt = 1.f / fmaxf(cnt, 1.f);
        for (int s = 0; s < NS; s++)
            coef[b * NS + s] = mask[s] * invcnt / g_sden[b * NS + s];
    }
    __syncthreads();
    int kr = 24, k0 = cid * kr;
    for (int i = tid; i < 8 * kr; i += 256) {
        int m = i / kr, kk = i - m * kr;
        float v = 0.f;
#pragma unroll
        for (int s = 0; s < NS; s++)
            v = fmaf(coef[m * NS + s], g_snum[((size_t)(m * NS + s)) * HD + k0 + kk], v);
        SM[i] = v;
    }
    __syncthreads();
    if (tid < HD4) {
        const float4* W4 = reinterpret_cast<const float4*>(w_v);
        float4 acc[8];
#pragma unroll
        for (int m = 0; m < 8; m++) acc[m] = make_float4(0.f, 0.f, 0.f, 0.f);
#pragma unroll 4
        for (int kk = 0; kk < 24; kk++) {
            float4 wv = W4[(size_t)(k0 + kk) * HD4 + tid];
#pragma unroll
            for (int m = 0; m < 8; m++) {
                float s = SM[m * 24 + kk];
                FMA4(acc[m], s, wv);
            }
        }
        int j = tid * 4;
#pragma unroll
        for (int m = 0; m < 8; m++) {
            atomicAdd(&g_ssum[(size_t)m * HD + j],     acc[m].x);
            atomicAdd(&g_ssum[(size_t)m * HD + j + 1], acc[m].y);
            atomicAdd(&g_ssum[(size_t)m * HD + j + 2], acc[m].z);
            atomicAdd(&g_ssum[(size_t)m * HD + j + 3], acc[m].w);
        }
    }
}

// grid 106: gi = w_ih @ tanh(cbk[idx]+ssum) computed in staging (74)
//           + OFF_SUM output/stop2 (8) + zero snum/sden (24)
__global__ void k_lm(const float* __restrict__ cbk, const float* __restrict__ w_ih,
                     const float* __restrict__ w_stop, float* __restrict__ out, int t) {
    __shared__ __align__(16) float SM[B * HD];
    __shared__ int sidx[B];
    __shared__ float SRED[8];
    int cid = blockIdx.x, tid = threadIdx.x, w = tid >> 5, lane = tid & 31;
    if (cid < 74) {
        if (tid < B) sidx[tid] = (int)(g_amin[tid] & 0xFFFFFFFFull);
        __syncthreads();
        for (int i = tid; i < B * HD; i += 256) {
            int m = i / HD, j = i - m * HD;
            SM[i] = tanhf(cbk[(size_t)sidx[m] * HD + j] + g_ssum[i]);
        }
        __syncthreads();
        rowdot4_body<8>(w_ih, g_gi, 3 * HD, 3 * HD, cid, 74, SM);
    } else if (cid < 82) {
        int b = cid - 74;
        int idx = (int)(g_amin[b] & 0xFFFFFFFFull);
        float sp = 0.f;
        for (int rep = 0; rep < 3; rep++) {
            int j = rep * 256 + tid;
            float ms = tanhf(cbk[(size_t)idx * HD + j] + g_ssum[b * HD + j]);
            out[OFF_SUM + ((size_t)b * TT + t) * HD + j] = ms;
            sp = fmaf(ms, w_stop[HD + j], sp);
        }
#pragma unroll
        for (int off = 16; off; off >>= 1) sp += __shfl_xor_sync(0xffffffffu, sp, off);
        if (lane == 0) SRED[w] = sp;
        __syncthreads();
        if (tid == 0) {
            float tot = 0.f;
#pragma unroll
            for (int q = 0; q < 8; q++) tot += SRED[q];
            atomicAdd(&g_stoplog[b], tot);
        }
    } else {
        for (int i = (cid - 82) * 256 + tid; i < B * NS * HD; i += 24 * 256)
            g_snum[i] = 0.f;
        if (cid == 82 && tid < B * NS) g_sden[tid] = 0.f;
    }
}

// grid 33: GRU combine (8) + SL/SP/CL (1) + zero ssum (24)
__global__ void k_m2(const float* __restrict__ stOld, float* __restrict__ stNew,
                     const float* __restrict__ b_ih, const float* __restrict__ b_hh,
                     const float* __restrict__ b_stop, float* __restrict__ out, int t) {
    int cid = blockIdx.x, tid = threadIdx.x;
    if (cid < 8) {
        int b = cid;
        for (int rep = 0; rep < 3; rep++) {
            int j = rep * 256 + tid;
            float ir = g_gi[b * 3 * HD + j] + b_ih[j];
            float iz = g_gi[b * 3 * HD + HD + j] + b_ih[HD + j];
            float in = g_gi[b * 3 * HD + 2 * HD + j] + b_ih[2 * HD + j];
            float hr = g_gh[b * 3 * HD + j] + b_hh[j];
            float hz = g_gh[b * 3 * HD + HD + j] + b_hh[HD + j];
            float hn = g_gh[b * 3 * HD + 2 * HD + j] + b_hh[2 * HD + j];
            float r = 1.f / (1.f + expf(-(ir + hr)));
            float z = 1.f / (1.f + expf(-(iz + hz)));
            float n = tanhf(in + r * hn);
            stNew[b * HD + j] = (1.f - z) * n + z * stOld[b * HD + j];
        }
    } else if (cid == 8) {
        if (tid == 0) {
            float bs = b_stop[0];
            for (int b = 0; b < B; b++) {
                float lg = g_stoplog[b] + bs;
                out[OFF_SL + b * TT + t] = lg;
                out[OFF_SP + b * TT + t] = 1.f / (1.f + expf(-lg));
                g_stoplog[b] = 0.f;
            }
            if (t == TT - 1) {
                for (int b = 0; b < B; b++) {
                    int len = TT;
                    for (int tt = 0; tt < TT; tt++)
                        if (out[OFF_SL + b * TT + tt] >= 0.f) { len = tt + 1; break; }
                    out[OFF_CL + b] = (float)len;
                }
            }
        }
    } else {
        int i = (cid - 9) * 256 + tid;
        g_ssum[i] = 0.f;
    }
}

// ---------------- host ----------------
extern "C" void kernel_launch(void* const* d_in, const int* in_sizes, int n_in,
                              void* d_out, int out_size) {
    const float* logic    = (const float*)d_in[0];
    const float* prompt   = (const float*)d_in[1];
    const float* cbk      = (const float*)d_in[2];
    const float* w_init   = (const float*)d_in[3];
    const float* w_q      = (const float*)d_in[4];
    const float* w_k      = (const float*)d_in[5];
    const float* w_v      = (const float*)d_in[6];
    const float* slot_q   = (const float*)d_in[7];
    const float* w_slot_q = (const float*)d_in[8];
    const float* w_op_pre = (const float*)d_in[9];
    const float* w_gate   = (const float*)d_in[10];
    const float* b_gate   = (const float*)d_in[11];
    const float* w_stop   = (const float*)d_in[12];
    const float* b_stop   = (const float*)d_in[13];
    const float* w_ih     = (const float*)d_in[14];
    const float* w_hh     = (const float*)d_in[15];
    const float* b_ih     = (const float*)d_in[16];
    const float* b_hh     = (const float*)d_in[17];
    float* out = (float*)d_out;

    void* p;
    float *stateA, *stateB;
    cudaGetSymbolAddress(&p, g_stateA); stateA = (float*)p;
    cudaGetSymbolAddress(&p, g_stateB); stateB = (float*)p;

    k_reset<<<32, 256>>>();
    k_pp1<<<12, 256>>>(prompt, logic);
    k_pp2<<<49, 256>>>(w_init, slot_q, w_slot_q, w_gate);
    k_pp3<<<148, 256>>>(w_k);

    for (int t = 0; t < TT; t++) {
        float* stOld = (t & 1) ? stateB : stateA;
        float* stNew = (t & 1) ? stateA : stateB;
        k_a<<<106, 256>>>(stOld, w_q, w_hh);
        k_b<<<96, 256>>>(w_k);
        k_cd<<<88, 256>>>(prompt);
        k_e<<<33, 256>>>(w_v);
        k_f<<<90, 256>>>(w_op_pre, w_slot_q, w_gate, w_stop);
        k_g<<<148, 256>>>(cbk, w_k, out, t);
        k_hs<<<88, 256>>>(prompt);
        k_k2<<<32, 256>>>(w_v, b_gate);
        k_lm<<<106, 256>>>(cbk, w_ih, w_stop, out, t);
        k_m2<<<33, 256>>>(stOld, stNew, b_ih, b_hh, b_stop, out, t);
    }
}

// round 13
// speedup vs baseline: 1.0197x; 1.0197x over previous
#include <cuda_runtime.h>
#include <math.h>

#define B    8
#define HD   768
#define HD4  192
#define LP   512
#define LL   256
#define CBN  4096
#define NS   9
#define TT   4

#define OFF_SUM 0
#define OFF_SL  24576
#define OFF_SP  24608
#define OFF_OP  24640
#define OFF_CL  155712

// ---------------- device scratch ----------------
__device__ __align__(16) float g_cat[B * 2 * HD];
__device__ __align__(16) float g_stateA[B * HD];
__device__ __align__(16) float g_stateB[B * HD];
__device__ __align__(16) float g_sq[B * HD];
__device__ __align__(16) float g_qprime[B * HD];
__device__ __align__(16) float g_unum[B * HD];
__device__ float g_Dnum[B];
__device__ __align__(16) float g_ctx[B * HD];
__device__ __align__(16) float g_oppre[B * HD];
__device__ __align__(16) float g_sq2[B * HD];
__device__ __align__(16) float g_qk2[B * HD];
__device__ __align__(16) float g_sqs[NS * HD];
__device__ __align__(16) float g_sqk2[NS * HD];
__device__ float g_gq[NS];
__device__ float g_glog[B];
__device__ __align__(16) float g_sscore[B * NS * LP];
__device__ __align__(16) float g_uslot[B * HD];
__device__ __align__(16) float g_ssum[B * HD];
__device__ __align__(16) float g_gi[B * 3 * HD];
__device__ __align__(16) float g_gh[B * 3 * HD];
__device__ float g_stoplog[B];
__device__ unsigned long long g_amin[B];

// ---------------- helpers ----------------

#define FMA4(ACC, A, Bv) \
    ACC.x = fmaf(A, Bv.x, ACC.x); ACC.y = fmaf(A, Bv.y, ACC.y); \
    ACC.z = fmaf(A, Bv.z, ACC.z); ACC.w = fmaf(A, Bv.w, ACC.w);

template <int M>
__device__ __forceinline__ void colgemv4(const float* __restrict__ X, int ldx,
                                         const float* __restrict__ W,
                                         float* __restrict__ Y,
                                         int K, int nks, int cid, float* SM) {
    int kr = K / nks, k0 = cid * kr;
    for (int i = threadIdx.x; i < M * kr; i += 256) {
        int m = i / kr, kk = i - m * kr;
        SM[i] = X[(size_t)m * ldx + k0 + kk];
    }
    __syncthreads();
    if (threadIdx.x < HD4) {
        const float4* W4 = reinterpret_cast<const float4*>(W);
        float4 acc[M];
#pragma unroll
        for (int m = 0; m < M; m++) acc[m] = make_float4(0.f, 0.f, 0.f, 0.f);
#pragma unroll 4
        for (int kk = 0; kk < kr; kk++) {
            float4 wv = W4[(size_t)(k0 + kk) * HD4 + threadIdx.x];
#pragma unroll
            for (int m = 0; m < M; m++) {
                float s = SM[m * kr + kk];
                FMA4(acc[m], s, wv);
            }
        }
        int j = threadIdx.x * 4;
#pragma unroll
        for (int m = 0; m < M; m++) {
            atomicAdd(&Y[(size_t)m * HD + j],     acc[m].x);
            atomicAdd(&Y[(size_t)m * HD + j + 1], acc[m].y);
            atomicAdd(&Y[(size_t)m * HD + j + 2], acc[m].z);
            atomicAdd(&Y[(size_t)m * HD + j + 3], acc[m].w);
        }
    }
}

template <int M>
__device__ __forceinline__ void rowdot(const float* __restrict__ W,
                                       const float* __restrict__ Xg,
                                       float* __restrict__ Y,
                                       int cid, int nc, float* SM) {
    int tid = threadIdx.x, w = tid >> 5, lane = tid & 31;
    for (int i = tid; i < M * HD; i += 256) SM[i] = Xg[i];
    __syncthreads();
    const float4* SM4 = reinterpret_cast<const float4*>(SM);
    for (int n = cid * 8 + w; n < HD; n += nc * 8) {
        const float4* wr = reinterpret_cast<const float4*>(W + (size_t)n * HD);
        float acc[M];
#pragma unroll
        for (int m = 0; m < M; m++) acc[m] = 0.f;
#pragma unroll
        for (int k = lane; k < HD4; k += 32) {
            float4 wv = wr[k];
#pragma unroll
            for (int m = 0; m < M; m++) {
                float4 s = SM4[m * HD4 + k];
                acc[m] = fmaf(wv.x, s.x, acc[m]);
                acc[m] = fmaf(wv.y, s.y, acc[m]);
                acc[m] = fmaf(wv.z, s.z, acc[m]);
                acc[m] = fmaf(wv.w, s.w, acc[m]);
            }
        }
#pragma unroll
        for (int m = 0; m < M; m++) {
#pragma unroll
            for (int off = 16; off; off >>= 1)
                acc[m] += __shfl_down_sync(0xffffffffu, acc[m], off);
        }
        if (lane == 0) {
#pragma unroll
            for (int m = 0; m < M; m++) Y[(size_t)m * HD + n] = acc[m];
        }
    }
}

// body only: SM must already hold M*HD staged values (synced)
template <int M>
__device__ __forceinline__ void rowdot4_body(const float* __restrict__ W,
                                             float* __restrict__ Y,
                                             int ldy, int Ntot,
                                             int cid, int nc, const float* SM) {
    int tid = threadIdx.x, w = tid >> 5, lane = tid & 31;
    const float4* SM4 = reinterpret_cast<const float4*>(SM);
    int stride = nc * 8;
    for (int n = cid * 8 + w; n < Ntot; n += 4 * stride) {
        int n1 = n + stride, n2 = n + 2 * stride, n3 = n + 3 * stride;
        bool q1 = n1 < Ntot, q2 = n2 < Ntot, q3 = n3 < Ntot;
        const float4* w0 = reinterpret_cast<const float4*>(W + (size_t)n * HD);
        const float4* w1 = reinterpret_cast<const float4*>(W + (size_t)(q1 ? n1 : n) * HD);
        const float4* w2 = reinterpret_cast<const float4*>(W + (size_t)(q2 ? n2 : n) * HD);
        const float4* w3 = reinterpret_cast<const float4*>(W + (size_t)(q3 ? n3 : n) * HD);
        float a0[M], a1[M], a2[M], a3[M];
#pragma unroll
        for (int m = 0; m < M; m++) { a0[m] = 0.f; a1[m] = 0.f; a2[m] = 0.f; a3[m] = 0.f; }
#pragma unroll 2
        for (int k = lane; k < HD4; k += 32) {
            float4 x0 = w0[k], x1 = w1[k], x2 = w2[k], x3 = w3[k];
#pragma unroll
            for (int m = 0; m < M; m++) {
                float4 s = SM4[m * HD4 + k];
                a0[m] = fmaf(x0.x, s.x, a0[m]); a0[m] = fmaf(x0.y, s.y, a0[m]);
                a0[m] = fmaf(x0.z, s.z, a0[m]); a0[m] = fmaf(x0.w, s.w, a0[m]);
                a1[m] = fmaf(x1.x, s.x, a1[m]); a1[m] = fmaf(x1.y, s.y, a1[m]);
                a1[m] = fmaf(x1.z, s.z, a1[m]); a1[m] = fmaf(x1.w, s.w, a1[m]);
                a2[m] = fmaf(x2.x, s.x, a2[m]); a2[m] = fmaf(x2.y, s.y, a2[m]);
                a2[m] = fmaf(x2.z, s.z, a2[m]); a2[m] = fmaf(x2.w, s.w, a2[m]);
                a3[m] = fmaf(x3.x, s.x, a3[m]); a3[m] = fmaf(x3.y, s.y, a3[m]);
                a3[m] = fmaf(x3.z, s.z, a3[m]); a3[m] = fmaf(x3.w, s.w, a3[m]);
            }
        }
#pragma unroll
        for (int m = 0; m < M; m++) {
            float v0 = a0[m], v1 = a1[m], v2 = a2[m], v3 = a3[m];
#pragma unroll
            for (int off = 16; off; off >>= 1) {
                v0 += __shfl_down_sync(0xffffffffu, v0, off);
                v1 += __shfl_down_sync(0xffffffffu, v1, off);
                v2 += __shfl_down_sync(0xffffffffu, v2, off);
                v3 += __shfl_down_sync(0xffffffffu, v3, off);
            }
            if (lane == 0) {
                Y[(size_t)m * ldy + n] = v0;
                if (q1) Y[(size_t)m * ldy + n1] = v1;
                if (q2) Y[(size_t)m * ldy + n2] = v2;
                if (q3) Y[(size_t)m * ldy + n3] = v3;
            }
        }
    }
}

template <int M>
__device__ __forceinline__ void rowdot4(const float* __restrict__ W,
                                        const float* __restrict__ Xg,
                                        float* __restrict__ Y,
                                        int ldy, int Ntot,
                                        int cid, int nc, float* SM) {
    for (int i = threadIdx.x; i < M * HD; i += 256) SM[i] = Xg[i];
    __syncthreads();
    rowdot4_body<M>(W, Y, ldy, Ntot, cid, nc, SM);
}

// ---------------- kernels ----------------

__global__ void k_reset() {
    int i = blockIdx.x * 256 + threadIdx.x;
    if (i < B * HD) {
        g_sq[i] = 0.f; g_unum[i] = 0.f; g_ctx[i] = 0.f; g_oppre[i] = 0.f;
        g_sq2[i] = 0.f; g_uslot[i] = 0.f; g_ssum[i] = 0.f;
    }
    if (i < NS * HD) g_sqs[i] = 0.f;
    if (i < B) { g_amin[i] = 0xFFFFFFFFFFFFFFFFull; g_stoplog[i] = 0.f; g_Dnum[i] = 0.f; }
}

__global__ void k_pp1(const float* __restrict__ prompt, const float* __restrict__ logic) {
    int w = threadIdx.x >> 5, lane = threadIdx.x & 31;
    int wt = blockIdx.x * 8 + w;
    if (wt < 48) {
        int b = wt / 6, hc = wt % 6;
        int h4 = hc * 32 + lane;
        const float4* p = reinterpret_cast<const float4*>(prompt + (size_t)b * LP * HD);
        float4 s = make_float4(0.f, 0.f, 0.f, 0.f);
#pragma unroll 8
        for (int l = 0; l < LP; l++) {
            float4 v = p[(size_t)l * HD4 + h4];
            s.x += v.x; s.y += v.y; s.z += v.z; s.w += v.w;
        }
        int h = h4 * 4;
        float inv = 1.f / (float)LP;
        g_cat[b * 2 * HD + h]     = s.x * inv;
        g_cat[b * 2 * HD + h + 1] = s.y * inv;
        g_cat[b * 2 * HD + h + 2] = s.z * inv;
        g_cat[b * 2 * HD + h + 3] = s.w * inv;
    } else {
        int t2 = wt - 48;
        int b = t2 / 6, hc = t2 % 6;
        int h4 = hc * 32 + lane;
        const float4* p = reinterpret_cast<const float4*>(logic + (size_t)b * LL * HD);
        float4 s = make_float4(0.f, 0.f, 0.f, 0.f);
#pragma unroll 8
        for (int l = 0; l < LL; l++) {
            float4 v = p[(size_t)l * HD4 + h4];
            s.x += v.x; s.y += v.y; s.z += v.z; s.w += v.w;
        }
        int h = h4 * 4;
        float inv = 1.f / (float)LL;
        g_cat[b * 2 * HD + HD + h]     = s.x * inv;
        g_cat[b * 2 * HD + HD + h + 1] = s.y * inv;
        g_cat[b * 2 * HD + HD + h + 2] = s.z * inv;
        g_cat[b * 2 * HD + HD + h + 3] = s.w * inv;
    }
}

__global__ void k_pp2(const float* __restrict__ w_init, const float* __restrict__ slot_q,
                      const float* __restrict__ w_slot_q, const float* __restrict__ w_gate) {
    __shared__ __align__(16) float SM[9 * 48];
    int cid = blockIdx.x, w = threadIdx.x >> 5, lane = threadIdx.x & 31;
    if (cid < 32) {
        colgemv4<8>(g_cat, 2 * HD, w_init, g_sq, 2 * HD, 32, cid, SM);
    } else if (cid < 48) {
        colgemv4<9>(slot_q, HD, w_slot_q, g_sqs, HD, 16, cid - 32, SM);
    } else {
        for (int s = w; s < NS; s += 8) {
            float p = 0.f;
            for (int k = lane; k < HD; k += 32)
                p = fmaf(slot_q[s * HD + k], w_gate[k], p);
#pragma unroll
            for (int off = 16; off; off >>= 1) p += __shfl_down_sync(0xffffffffu, p, off);
            if (lane == 0) g_gq[s] = p;
        }
    }
}

__global__ void k_pp3(const float* __restrict__ w_k) {
    __shared__ __align__(16) float SM[NS * HD];
    int cid = blockIdx.x, tid = threadIdx.x;
    if (cid < 8) {
        int b = cid;
        for (int rep = 0; rep < 3; rep++) {
            int j = rep * 256 + tid;
            g_stateA[b * HD + j] = tanhf(g_sq[b * HD + j]);
            g_sq[b * HD + j] = 0.f;
        }
    } else {
        rowdot<9>(w_k, g_sqs, g_sqk2, cid - 8, 140, SM);
    }
}

// grid 106: sq += state@w_q (32) + gh = w_hh@stOld (74)
__global__ void k_a(const float* __restrict__ st, const float* __restrict__ w_q,
                    const float* __restrict__ w_hh) {
    __shared__ __align__(16) float SM[B * HD];
    if (blockIdx.x < 32) colgemv4<8>(st, HD, w_q, g_sq, HD, 32, blockIdx.x, SM);
    else rowdot4<8>(w_hh, st, g_gh, 3 * HD, 3 * HD, blockIdx.x - 32, 74, SM);
}

// grid 96: qprime = w_k @ sq
__global__ void k_b(const float* __restrict__ w_k) {
    __shared__ __align__(16) float SM[8 * HD];
    rowdot<8>(w_k, g_sq, g_qprime, blockIdx.x, 96, SM);
}

// grid 88: fused state scores + exp + weighted prompt accum (64) + zero sq (24)
__global__ void k_cd(const float* __restrict__ prompt) {
    int cid = blockIdx.x, tid = threadIdx.x, w = tid >> 5, lane = tid & 31;
    const float scale = 0.03608439182435161f;
    if (cid < 64) {
        __shared__ __align__(16) float su[4 * HD];
        __shared__ float sD[8];
        int b = cid >> 3, ch = cid & 7;
        const float4* qp4 = reinterpret_cast<const float4*>(g_qprime + b * HD);
        float4 qv[6];
#pragma unroll
        for (int q = 0; q < 6; q++) qv[q] = qp4[q * 32 + lane];
        float4 acc[6];
#pragma unroll
        for (int q = 0; q < 6; q++) acc[q] = make_float4(0.f, 0.f, 0.f, 0.f);
        float Dw = 0.f;
        const float4* pr = reinterpret_cast<const float4*>(
            prompt + ((size_t)(b * LP + ch * 64)) * HD);
        for (int r = 0; r < 8; r++) {
            int l = w * 8 + r;
            const float4* row = pr + (size_t)l * HD4;
            float4 pv[6];
#pragma unroll
            for (int q = 0; q < 6; q++) pv[q] = row[q * 32 + lane];
            float s = 0.f;
#pragma unroll
            for (int q = 0; q < 6; q++) {
                s = fmaf(pv[q].x, qv[q].x, s); s = fmaf(pv[q].y, qv[q].y, s);
                s = fmaf(pv[q].z, qv[q].z, s); s = fmaf(pv[q].w, qv[q].w, s);
            }
#pragma unroll
            for (int off = 16; off; off >>= 1) s += __shfl_xor_sync(0xffffffffu, s, off);
            float e = expf(s * scale);
            Dw += e;
#pragma unroll
            for (int q = 0; q < 6; q++) { FMA4(acc[q], e, pv[q]); }
        }
        float4* su4 = reinterpret_cast<float4*>(su);
        if (w < 4) {
#pragma unroll
            for (int q = 0; q < 6; q++) su4[w * HD4 + q * 32 + lane] = acc[q];
        }
        if (lane == 0) sD[w] = Dw;
        __syncthreads();
        if (w >= 4) {
#pragma unroll
            for (int q = 0; q < 6; q++) {
                float4 t = su4[(w - 4) * HD4 + q * 32 + lane];
                t.x += acc[q].x; t.y += acc[q].y; t.z += acc[q].z; t.w += acc[q].w;
                su4[(w - 4) * HD4 + q * 32 + lane] = t;
            }
        }
        __syncthreads();
        for (int r = 0; r < 3; r++) {
            int j = r * 256 + tid;
            float v = su[j] + su[HD + j] + su[2 * HD + j] + su[3 * HD + j];
            atomicAdd(&g_unum[b * HD + j], v);
        }
        if (tid == 0) {
            float d = sD[0] + sD[1] + sD[2] + sD[3] + sD[4] + sD[5] + sD[6] + sD[7];
            atomicAdd(&g_Dnum[b], d);
        }
    } else {
        int i = (cid - 64) * 256 + tid;
        g_sq[i] = 0.f;
    }
}

// grid 33: ctx += (unum/D) @ w_v (32) + reset amin (1)
__global__ void k_e(const float* __restrict__ w_v) {
    __shared__ __align__(16) float SM[8 * 24];
    if (blockIdx.x < 32) {
        int cid = blockIdx.x;
        int kr = 24, k0 = cid * kr;
        for (int i = threadIdx.x; i < 8 * kr; i += 256) {
            int m = i / kr, kk = i - m * kr;
            SM[i] = g_unum[m * HD + k0 + kk] / g_Dnum[m];
        }
        __syncthreads();
        if (threadIdx.x < HD4) {
            const float4* W4 = reinterpret_cast<const float4*>(w_v);
            float4 acc[8];
#pragma unroll
            for (int m = 0; m < 8; m++) acc[m] = make_float4(0.f, 0.f, 0.f, 0.f);
#pragma unroll 4
            for (int kk = 0; kk < 24; kk++) {
                float4 wv = W4[(size_t)(k0 + kk) * HD4 + threadIdx.x];
#pragma unroll
                for (int m = 0; m < 8; m++) {
                    float s = SM[m * 24 + kk];
                    FMA4(acc[m], s, wv);
                }
            }
            int j = threadIdx.x * 4;
#pragma unroll
            for (int m = 0; m < 8; m++) {
                atomicAdd(&g_ctx[(size_t)m * HD + j],     acc[m].x);
                atomicAdd(&g_ctx[(size_t)m * HD + j + 1], acc[m].y);
                atomicAdd(&g_ctx[(size_t)m * HD + j + 2], acc[m].z);
                atomicAdd(&g_ctx[(size_t)m * HD + j + 3], acc[m].w);
            }
        }
    } else if (threadIdx.x < B) g_amin[threadIdx.x] = 0xFFFFFFFFFFFFFFFFull;
}

// grid 90: oppre (32), sq2 (32), glog (1), stop1 (1), zero unum/Dnum (24)
__global__ void k_f(const float* __restrict__ w_op_pre, const float* __restrict__ w_slot_q,
                    const float* __restrict__ w_gate, const float* __restrict__ w_stop) {
    __shared__ __align__(16) float SM[8 * 24];
    int cid = blockIdx.x, w = threadIdx.x >> 5, lane = threadIdx.x & 31;
    if (cid < 32) colgemv4<8>(g_ctx, HD, w_op_pre, g_oppre, HD, 32, cid, SM);
    else if (cid < 64) colgemv4<8>(g_ctx, HD, w_slot_q, g_sq2, HD, 32, cid - 32, SM);
    else if (cid == 64) {
        int b = w;
        float p = 0.f;
        for (int k = lane; k < HD; k += 32) p = fmaf(g_ctx[b * HD + k], w_gate[k], p);
#pragma unroll
        for (int off = 16; off; off >>= 1) p += __shfl_down_sync(0xffffffffu, p, off);
        if (lane == 0) g_glog[b] = p;
    } else if (cid == 65) {
        int b = w;
        float p = 0.f;
        for (int k = lane; k < HD; k += 32) p = fmaf(g_ctx[b * HD + k], w_stop[k], p);
#pragma unroll
        for (int off = 16; off; off >>= 1) p += __shfl_down_sync(0xffffffffu, p, off);
        if (lane == 0) g_stoplog[b] = p;
    } else {
        int i = (cid - 66) * 256 + threadIdx.x;
        g_unum[i] = 0.f;
        if (cid == 66 && threadIdx.x < B) g_Dnum[threadIdx.x] = 0.f;
    }
}

// grid 148: codebook (118) + qk2 = w_k@sq2 (30)
__global__ void k_g(const float* __restrict__ cbk, const float* __restrict__ w_k,
                    float* __restrict__ out, int t) {
    __shared__ __align__(16) float SM[B * HD];
    int cid = blockIdx.x, tid = threadIdx.x, w = tid >> 5, lane = tid & 31;
    if (cid < 118) {
        for (int i = tid; i < B * HD; i += 256) SM[i] = g_oppre[i];
        __syncthreads();
        const float4* SM4 = reinterpret_cast<const float4*>(SM);
        for (int c0 = cid * 8 + w; c0 < CBN; c0 += 2 * 944) {
            int c1 = c0 + 944;
            bool q1 = c1 < CBN;
            const float4* r0 = reinterpret_cast<const float4*>(cbk + (size_t)c0 * HD);
            const float4* r1 = reinterpret_cast<const float4*>(cbk + (size_t)(q1 ? c1 : c0) * HD);
            float a0[B], a1[B];
#pragma unroll
            for (int m = 0; m < B; m++) { a0[m] = 0.f; a1[m] = 0.f; }
#pragma unroll 2
            for (int k = lane; k < HD4; k += 32) {
                float4 x0 = r0[k], x1 = r1[k];
#pragma unroll
                for (int m = 0; m < B; m++) {
                    float4 sv = SM4[m * HD4 + k];
                    float d;
                    d = sv.x - x0.x; a0[m] = fmaf(d, d, a0[m]);
                    d = sv.y - x0.y; a0[m] = fmaf(d, d, a0[m]);
                    d = sv.z - x0.z; a0[m] = fmaf(d, d, a0[m]);
                    d = sv.w - x0.w; a0[m] = fmaf(d, d, a0[m]);
                    d = sv.x - x1.x; a1[m] = fmaf(d, d, a1[m]);
                    d = sv.y - x1.y; a1[m] = fmaf(d, d, a1[m]);
                    d = sv.z - x1.z; a1[m] = fmaf(d, d, a1[m]);
                    d = sv.w - x1.w; a1[m] = fmaf(d, d, a1[m]);
                }
            }
#pragma unroll
            for (int m = 0; m < B; m++) {
                float v0 = a0[m], v1 = a1[m];
#pragma unroll
                for (int off = 16; off; off >>= 1) {
                    v0 += __shfl_down_sync(0xffffffffu, v0, off);
                    v1 += __shfl_down_sync(0xffffffffu, v1, off);
                }
                if (lane == 0) {
                    out[OFF_OP + ((size_t)m * TT + t) * CBN + c0] = -v0;
                    unsigned long long key0 =
                        ((unsigned long long)__float_as_uint(v0) << 32) | (unsigned)c0;
                    atomicMin(&g_amin[m], key0);
                    if (q1) {
                        out[OFF_OP + ((size_t)m * TT + t) * CBN + c1] = -v1;
                        unsigned long long key1 =
                            ((unsigned long long)__float_as_uint(v1) << 32) | (unsigned)c1;
                        atomicMin(&g_amin[m], key1);
                    }
                }
            }
        }
    } else {
        rowdot4<8>(w_k, g_sq2, g_qk2, HD, HD, cid - 118, 30, SM);
    }
}

// grid 148: slot scores (128) + zero ctx/oppre/sq2 (20)
__global__ void k_h(const float* __restrict__ prompt) {
    __shared__ __align__(16) float SM[NS * HD];
    int cid = blockIdx.x, tid = threadIdx.x, w = tid >> 5, lane = tid & 31;
    const float scale = 0.03608439182435161f;
    if (cid < 128) {
        int b = cid >> 4, lc = cid & 15;
        for (int i = tid; i < NS * HD; i += 256) {
            int k = i % HD;
            SM[i] = g_qk2[b * HD + k] + g_sqk2[i];
        }
        __syncthreads();
        const float4* SM4 = reinterpret_cast<const float4*>(SM);
        int l0 = lc * 32 + w * 4;
        const float4* p0 = reinterpret_cast<const float4*>(prompt + ((size_t)(b * LP + l0)) * HD);
        float a0[NS], a1[NS], a2[NS], a3[NS];
#pragma unroll
        for (int s = 0; s < NS; s++) { a0[s] = 0.f; a1[s] = 0.f; a2[s] = 0.f; a3[s] = 0.f; }
#pragma unroll 2
        for (int k = lane; k < HD4; k += 32) {
            float4 v0 = p0[k], v1 = p0[HD4 + k], v2 = p0[2 * HD4 + k], v3 = p0[3 * HD4 + k];
#pragma unroll
            for (int s = 0; s < NS; s++) {
                float4 q = SM4[s * HD4 + k];
                a0[s] = fmaf(v0.x, q.x, a0[s]); a0[s] = fmaf(v0.y, q.y, a0[s]);
                a0[s] = fmaf(v0.z, q.z, a0[s]); a0[s] = fmaf(v0.w, q.w, a0[s]);
                a1[s] = fmaf(v1.x, q.x, a1[s]); a1[s] = fmaf(v1.y, q.y, a1[s]);
                a1[s] = fmaf(v1.z, q.z, a1[s]); a1[s] = fmaf(v1.w, q.w, a1[s]);
                a2[s] = fmaf(v2.x, q.x, a2[s]); a2[s] = fmaf(v2.y, q.y, a2[s]);
                a2[s] = fmaf(v2.z, q.z, a2[s]); a2[s] = fmaf(v2.w, q.w, a2[s]);
                a3[s] = fmaf(v3.x, q.x, a3[s]); a3[s] = fmaf(v3.y, q.y, a3[s]);
                a3[s] = fmaf(v3.z, q.z, a3[s]); a3[s] = fmaf(v3.w, q.w, a3[s]);
            }
        }
#pragma unroll
        for (int s = 0; s < NS; s++) {
            float v0 = a0[s], v1 = a1[s], v2 = a2[s], v3 = a3[s];
#pragma unroll
            for (int off = 16; off; off >>= 1) {
                v0 += __shfl_down_sync(0xffffffffu, v0, off);
                v1 += __shfl_down_sync(0xffffffffu, v1, off);
                v2 += __shfl_down_sync(0xffffffffu, v2, off);
                v3 += __shfl_down_sync(0xffffffffu, v3, off);
            }
            if (lane == 0) {
                float* dst = &g_sscore[(size_t)(b * NS + s) * LP + l0];
                dst[0] = v0 * scale;
                dst[1] = v1 * scale;
                dst[2] = v2 * scale;
                dst[3] = v3 * scale;
            }
        }
    } else {
        for (int i = (cid - 128) * 256 + tid; i < 3 * B * HD; i += 20 * 256) {
            if (i < B * HD) g_ctx[i] = 0.f;
            else if (i < 2 * B * HD) g_oppre[i - B * HD] = 0.f;
            else g_sq2[i - 2 * B * HD] = 0.f;
        }
    }
}

// grid 64: fused collapse (replicated) + weighted prompt sweep -> uslot
__global__ void k_jp(const float* __restrict__ prompt, const float* __restrict__ b_gate) {
    __shared__ float SS[NS * LP];
    __shared__ __align__(16) float su[4 * HD];
    __shared__ float sred[NS];
    __shared__ float coef[NS];
    __shared__ float wrow[64];
    int cid = blockIdx.x, tid = threadIdx.x, w = tid >> 5, lane = tid & 31;
    int b = cid >> 3, ch = cid & 7;
    for (int i = tid; i < NS * LP; i += 256) SS[i] = expf(g_sscore[(size_t)b * NS * LP + i]);
    __syncthreads();
    for (int s = w; s < NS; s += 8) {
        float p = 0.f;
        for (int l = lane; l < LP; l += 32) p += SS[s * LP + l];
#pragma unroll
        for (int off = 16; off; off >>= 1) p += __shfl_down_sync(0xffffffffu, p, off);
        if (lane == 0) sred[s] = p;
    }
    __syncthreads();
    if (tid == 0) {
        float bg = b_gate[0];
        bool any = false;
        for (int bb = 0; bb < B; bb++)
            for (int s = 0; s < NS; s++)
                if (g_glog[bb] + g_gq[s] + bg >= 0.f) any = true;
        float mask[NS], cnt = 0.f;
        if (any) {
            for (int s = 0; s < NS; s++) {
                float m = (g_glog[b] + g_gq[s] + bg >= 0.f) ? 1.f : 0.f;
                mask[s] = m; cnt += m;
            }
        } else {
            int arg = 0; float best = g_glog[b] + g_gq[0] + bg;
            for (int s = 1; s < NS; s++) {
                float v = g_glog[b] + g_gq[s] + bg;
                if (v > best) { best = v; arg = s; }
            }
            for (int s = 0; s < NS; s++) mask[s] = (s == arg) ? 1.f : 0.f;
            cnt = 1.f;
        }
        float invcnt = 1.f / fmaxf(cnt, 1.f);
        for (int s = 0; s < NS; s++) coef[s] = mask[s] * invcnt / sred[s];
    }
    __syncthreads();
    if (tid < 64) {
        int l = ch * 64 + tid;
        float ww = 0.f;
#pragma unroll
        for (int s = 0; s < NS; s++) ww = fmaf(coef[s], SS[s * LP + l], ww);
        wrow[tid] = ww;
    }
    __syncthreads();
    float4 acc[6];
#pragma unroll
    for (int q = 0; q < 6; q++) acc[q] = make_float4(0.f, 0.f, 0.f, 0.f);
    const float4* pr = reinterpret_cast<const float4*>(prompt + ((size_t)(b * LP + ch * 64)) * HD);
    for (int r = 0; r < 8; r++) {
        int l = w * 8 + r;
        float wt = wrow[l];
        const float4* row = pr + (size_t)l * HD4;
#pragma unroll
        for (int q = 0; q < 6; q++) {
            float4 pv = row[q * 32 + lane];
            FMA4(acc[q], wt, pv);
        }
    }
    float4* su4 = reinterpret_cast<float4*>(su);
    if (w < 4) {
#pragma unroll
        for (int q = 0; q < 6; q++) su4[w * HD4 + q * 32 + lane] = acc[q];
    }
    __syncthreads();
    if (w >= 4) {
#pragma unroll
        for (int q = 0; q < 6; q++) {
            float4 t = su4[(w - 4) * HD4 + q * 32 + lane];
            t.x += acc[q].x; t.y += acc[q].y; t.z += acc[q].z; t.w += acc[q].w;
            su4[(w - 4) * HD4 + q * 32 + lane] = t;
        }
    }
    __syncthreads();
    for (int r = 0; r < 3; r++) {
        int j = r * 256 + tid;
        float v = su[j] + su[HD + j] + su[2 * HD + j] + su[3 * HD + j];
        atomicAdd(&g_uslot[b * HD + j], v);
    }
}

// grid 32: ssum += uslot @ w_v
__global__ void k_k(const float* __restrict__ w_v) {
    __shared__ __align__(16) float SM[8 * 24];
    colgemv4<8>(g_uslot, HD, w_v, g_ssum, HD, 32, blockIdx.x, SM);
}

// grid 106: gi = w_ih @ tanh(cbk[idx]+ssum) in staging (74)
//           + OFF_SUM output/stop2 (8) + zero uslot (24)
__global__ void k_lm(const float* __restrict__ cbk, const float* __restrict__ w_ih,
                     const float* __restrict__ w_stop, float* __restrict__ out, int t) {
    __shared__ __align__(16) float SM[B * HD];
    __shared__ int sidx[B];
    __shared__ float SRED[8];
    int cid = blockIdx.x, tid = threadIdx.x, w = tid >> 5, lane = tid & 31;
    if (cid < 74) {
        if (tid < B) sidx[tid] = (int)(g_amin[tid] & 0xFFFFFFFFull);
        __syncthreads();
        for (int i = tid; i < B * HD; i += 256) {
            int m = i / HD, j = i - m * HD;
            SM[i] = tanhf(cbk[(size_t)sidx[m] * HD + j] + g_ssum[i]);
        }
        __syncthreads();
        rowdot4_body<8>(w_ih, g_gi, 3 * HD, 3 * HD, cid, 74, SM);
    } else if (cid < 82) {
        int b = cid - 74;
        int idx = (int)(g_amin[b] & 0xFFFFFFFFull);
        float sp = 0.f;
        for (int rep = 0; rep < 3; rep++) {
            int j = rep * 256 + tid;
            float ms = tanhf(cbk[(size_t)idx * HD + j] + g_ssum[b * HD + j]);
            out[OFF_SUM + ((size_t)b * TT + t) * HD + j] = ms;
            sp = fmaf(ms, w_stop[HD + j], sp);
        }
#pragma unroll
        for (int off = 16; off; off >>= 1) sp += __shfl_xor_sync(0xffffffffu, sp, off);
        if (lane == 0) SRED[w] = sp;
        __syncthreads();
        if (tid == 0) {
            float tot = 0.f;
#pragma unroll
            for (int q = 0; q < 8; q++) tot += SRED[q];
            atomicAdd(&g_stoplog[b], tot);
        }
    } else {
        int i = (cid - 82) * 256 + tid;
        if (i < B * HD) g_uslot[i] = 0.f;
    }
}

// grid 33: GRU combine (8) + SL/SP/CL (1) + zero ssum (24)
__global__ void k_m2(const float* __restrict__ stOld, float* __restrict__ stNew,
                     const float* __restrict__ b_ih, const float* __restrict__ b_hh,
                     const float* __restrict__ b_stop, float* __restrict__ out, int t) {
    int cid = blockIdx.x, tid = threadIdx.x;
    if (cid < 8) {
        int b = cid;
        for (int rep = 0; rep < 3; rep++) {
            int j = rep * 256 + tid;
            float ir = g_gi[b * 3 * HD + j] + b_ih[j];
            float iz = g_gi[b * 3 * HD + HD + j] + b_ih[HD + j];
            float in = g_gi[b * 3 * HD + 2 * HD + j] + b_ih[2 * HD + j];
            float hr = g_gh[b * 3 * HD + j] + b_hh[j];
            float hz = g_gh[b * 3 * HD + HD + j] + b_hh[HD + j];
            float hn = g_gh[b * 3 * HD + 2 * HD + j] + b_hh[2 * HD + j];
            float r = 1.f / (1.f + expf(-(ir + hr)));
            float z = 1.f / (1.f + expf(-(iz + hz)));
            float n = tanhf(in + r * hn);
            stNew[b * HD + j] = (1.f - z) * n + z * stOld[b * HD + j];
        }
    } else if (cid == 8) {
        if (tid == 0) {
            float bs = b_stop[0];
            for (int b = 0; b < B; b++) {
                float lg = g_stoplog[b] + bs;
                out[OFF_SL + b * TT + t] = lg;
                out[OFF_SP + b * TT + t] = 1.f / (1.f + expf(-lg));
                g_stoplog[b] = 0.f;
            }
            if (t == TT - 1) {
                for (int b = 0; b < B; b++) {
                    int len = TT;
                    for (int tt = 0; tt < TT; tt++)
                        if (out[OFF_SL + b * TT + tt] >= 0.f) { len = tt + 1; break; }
                    out[OFF_CL + b] = (float)len;
                }
            }
        }
    } else {
        int i = (cid - 9) * 256 + tid;
        g_ssum[i] = 0.f;
    }
}

// ---------------- host ----------------
extern "C" void kernel_launch(void* const* d_in, const int* in_sizes, int n_in,
                              void* d_out, int out_size) {
    const float* logic    = (const float*)d_in[0];
    const float* prompt   = (const float*)d_in[1];
    const float* cbk      = (const float*)d_in[2];
    const float* w_init   = (const float*)d_in[3];
    const float* w_q      = (const float*)d_in[4];
    const float* w_k      = (const float*)d_in[5];
    const float* w_v      = (const float*)d_in[6];
    const float* slot_q   = (const float*)d_in[7];
    const float* w_slot_q = (const float*)d_in[8];
    const float* w_op_pre = (const float*)d_in[9];
    const float* w_gate   = (const float*)d_in[10];
    const float* b_gate   = (const float*)d_in[11];
    const float* w_stop   = (const float*)d_in[12];
    const float* b_stop   = (const float*)d_in[13];
    const float* w_ih     = (const float*)d_in[14];
    const float* w_hh     = (const float*)d_in[15];
    const float* b_ih     = (const float*)d_in[16];
    const float* b_hh     = (const float*)d_in[17];
    float* out = (float*)d_out;

    void* p;
    float *stateA, *stateB;
    cudaGetSymbolAddress(&p, g_stateA); stateA = (float*)p;
    cudaGetSymbolAddress(&p, g_stateB); stateB = (float*)p;

    k_reset<<<28, 256>>>();
    k_pp1<<<12, 256>>>(prompt, logic);
    k_pp2<<<49, 256>>>(w_init, slot_q, w_slot_q, w_gate);
    k_pp3<<<148, 256>>>(w_k);

    for (int t = 0; t < TT; t++) {
        float* stOld = (t & 1) ? stateB : stateA;
        float* stNew = (t & 1) ? stateA : stateB;
        k_a<<<106, 256>>>(stOld, w_q, w_hh);
        k_b<<<96, 256>>>(w_k);
        k_cd<<<88, 256>>>(prompt);
        k_e<<<33, 256>>>(w_v);
        k_f<<<90, 256>>>(w_op_pre, w_slot_q, w_gate, w_stop);
        k_g<<<148, 256>>>(cbk, w_k, out, t);
        k_h<<<148, 256>>>(prompt);
        k_jp<<<64, 256>>>(prompt, b_gate);
        k_k<<<32, 256>>>(w_v);
        k_lm<<<106, 256>>>(cbk, w_ih, w_stop, out, t);
        k_m2<<<33, 256>>>(stOld, stNew, b_ih, b_hh, b_stop, out, t);
    }
}

// round 14
// speedup vs baseline: 1.0671x; 1.0465x over previous
#include <cuda_runtime.h>
#include <math.h>

#define B    8
#define HD   768
#define HD4  192
#define LP   512
#define LL   256
#define CBN  4096
#define NS   9
#define TT   4

#define OFF_SUM 0
#define OFF_SL  24576
#define OFF_SP  24608
#define OFF_OP  24640
#define OFF_CL  155712

// ---------------- device scratch ----------------
__device__ __align__(16) float g_cat[B * 2 * HD];
__device__ __align__(16) float g_stateA[B * HD];
__device__ __align__(16) float g_stateB[B * HD];
__device__ __align__(16) float g_sq[B * HD];
__device__ __align__(16) float g_qprime[B * HD];
__device__ __align__(16) float g_unum[B * HD];
__device__ float g_Dnum[B];
__device__ __align__(16) float g_ctx[B * HD];
__device__ __align__(16) float g_oppre[B * HD];
__device__ __align__(16) float g_sq2[B * HD];
__device__ __align__(16) float g_qk2[B * HD];
__device__ __align__(16) float g_sqs[NS * HD];
__device__ __align__(16) float g_sqk2[NS * HD];
__device__ float g_gq[NS];
__device__ float g_glog[B];
__device__ __align__(16) float g_sscore[B * NS * LP];
__device__ __align__(16) float g_uslot[B * HD];
__device__ __align__(16) float g_ssum[B * HD];
__device__ __align__(16) float g_msum[B * HD];
__device__ __align__(16) float g_gi[B * 3 * HD];
__device__ __align__(16) float g_gh[B * 3 * HD];
__device__ float g_stoplog[B];
__device__ unsigned long long g_amin[B];

// ---------------- helpers ----------------

#define FMA4(ACC, A, Bv) \
    ACC.x = fmaf(A, Bv.x, ACC.x); ACC.y = fmaf(A, Bv.y, ACC.y); \
    ACC.z = fmaf(A, Bv.z, ACC.z); ACC.w = fmaf(A, Bv.w, ACC.w);

template <int M>
__device__ __forceinline__ void colgemv4(const float* __restrict__ X, int ldx,
                                         const float* __restrict__ W,
                                         float* __restrict__ Y,
                                         int K, int nks, int cid, float* SM) {
    int kr = K / nks, k0 = cid * kr;
    for (int i = threadIdx.x; i < M * kr; i += 256) {
        int m = i / kr, kk = i - m * kr;
        SM[i] = X[(size_t)m * ldx + k0 + kk];
    }
    __syncthreads();
    if (threadIdx.x < HD4) {
        const float4* W4 = reinterpret_cast<const float4*>(W);
        float4 acc[M];
#pragma unroll
        for (int m = 0; m < M; m++) acc[m] = make_float4(0.f, 0.f, 0.f, 0.f);
#pragma unroll 4
        for (int kk = 0; kk < kr; kk++) {
            float4 wv = W4[(size_t)(k0 + kk) * HD4 + threadIdx.x];
#pragma unroll
            for (int m = 0; m < M; m++) {
                float s = SM[m * kr + kk];
                FMA4(acc[m], s, wv);
            }
        }
        int j = threadIdx.x * 4;
#pragma unroll
        for (int m = 0; m < M; m++) {
            atomicAdd(&Y[(size_t)m * HD + j],     acc[m].x);
            atomicAdd(&Y[(size_t)m * HD + j + 1], acc[m].y);
            atomicAdd(&Y[(size_t)m * HD + j + 2], acc[m].z);
            atomicAdd(&Y[(size_t)m * HD + j + 3], acc[m].w);
        }
    }
}

template <int M>
__device__ __forceinline__ void rowdot(const float* __restrict__ W,
                                       const float* __restrict__ Xg,
                                       float* __restrict__ Y,
                                       int cid, int nc, float* SM) {
    int tid = threadIdx.x, w = tid >> 5, lane = tid & 31;
    for (int i = tid; i < M * HD; i += 256) SM[i] = Xg[i];
    __syncthreads();
    const float4* SM4 = reinterpret_cast<const float4*>(SM);
    for (int n = cid * 8 + w; n < HD; n += nc * 8) {
        const float4* wr = reinterpret_cast<const float4*>(W + (size_t)n * HD);
        float acc[M];
#pragma unroll
        for (int m = 0; m < M; m++) acc[m] = 0.f;
#pragma unroll
        for (int k = lane; k < HD4; k += 32) {
            float4 wv = wr[k];
#pragma unroll
            for (int m = 0; m < M; m++) {
                float4 s = SM4[m * HD4 + k];
                acc[m] = fmaf(wv.x, s.x, acc[m]);
                acc[m] = fmaf(wv.y, s.y, acc[m]);
                acc[m] = fmaf(wv.z, s.z, acc[m]);
                acc[m] = fmaf(wv.w, s.w, acc[m]);
            }
        }
#pragma unroll
        for (int m = 0; m < M; m++) {
#pragma unroll
            for (int off = 16; off; off >>= 1)
                acc[m] += __shfl_down_sync(0xffffffffu, acc[m], off);
        }
        if (lane == 0) {
#pragma unroll
            for (int m = 0; m < M; m++) Y[(size_t)m * HD + n] = acc[m];
        }
    }
}

// body only: SM must already hold M*HD staged values (synced)
template <int M>
__device__ __forceinline__ void rowdot4_body(const float* __restrict__ W,
                                             float* __restrict__ Y,
                                             int ldy, int Ntot,
                                             int cid, int nc, const float* SM) {
    int tid = threadIdx.x, w = tid >> 5, lane = tid & 31;
    const float4* SM4 = reinterpret_cast<const float4*>(SM);
    int stride = nc * 8;
    for (int n = cid * 8 + w; n < Ntot; n += 4 * stride) {
        int n1 = n + stride, n2 = n + 2 * stride, n3 = n + 3 * stride;
        bool q1 = n1 < Ntot, q2 = n2 < Ntot, q3 = n3 < Ntot;
        const float4* w0 = reinterpret_cast<const float4*>(W + (size_t)n * HD);
        const float4* w1 = reinterpret_cast<const float4*>(W + (size_t)(q1 ? n1 : n) * HD);
        const float4* w2 = reinterpret_cast<const float4*>(W + (size_t)(q2 ? n2 : n) * HD);
        const float4* w3 = reinterpret_cast<const float4*>(W + (size_t)(q3 ? n3 : n) * HD);
        float a0[M], a1[M], a2[M], a3[M];
#pragma unroll
        for (int m = 0; m < M; m++) { a0[m] = 0.f; a1[m] = 0.f; a2[m] = 0.f; a3[m] = 0.f; }
#pragma unroll 2
        for (int k = lane; k < HD4; k += 32) {
            float4 x0 = w0[k], x1 = w1[k], x2 = w2[k], x3 = w3[k];
#pragma unroll
            for (int m = 0; m < M; m++) {
                float4 s = SM4[m * HD4 + k];
                a0[m] = fmaf(x0.x, s.x, a0[m]); a0[m] = fmaf(x0.y, s.y, a0[m]);
                a0[m] = fmaf(x0.z, s.z, a0[m]); a0[m] = fmaf(x0.w, s.w, a0[m]);
                a1[m] = fmaf(x1.x, s.x, a1[m]); a1[m] = fmaf(x1.y, s.y, a1[m]);
                a1[m] = fmaf(x1.z, s.z, a1[m]); a1[m] = fmaf(x1.w, s.w, a1[m]);
                a2[m] = fmaf(x2.x, s.x, a2[m]); a2[m] = fmaf(x2.y, s.y, a2[m]);
                a2[m] = fmaf(x2.z, s.z, a2[m]); a2[m] = fmaf(x2.w, s.w, a2[m]);
                a3[m] = fmaf(x3.x, s.x, a3[m]); a3[m] = fmaf(x3.y, s.y, a3[m]);
                a3[m] = fmaf(x3.z, s.z, a3[m]); a3[m] = fmaf(x3.w, s.w, a3[m]);
            }
        }
#pragma unroll
        for (int m = 0; m < M; m++) {
            float v0 = a0[m], v1 = a1[m], v2 = a2[m], v3 = a3[m];
#pragma unroll
            for (int off = 16; off; off >>= 1) {
                v0 += __shfl_down_sync(0xffffffffu, v0, off);
                v1 += __shfl_down_sync(0xffffffffu, v1, off);
                v2 += __shfl_down_sync(0xffffffffu, v2, off);
                v3 += __shfl_down_sync(0xffffffffu, v3, off);
            }
            if (lane == 0) {
                Y[(size_t)m * ldy + n] = v0;
                if (q1) Y[(size_t)m * ldy + n1] = v1;
                if (q2) Y[(size_t)m * ldy + n2] = v2;
                if (q3) Y[(size_t)m * ldy + n3] = v3;
            }
        }
    }
}

template <int M>
__device__ __forceinline__ void rowdot4(const float* __restrict__ W,
                                        const float* __restrict__ Xg,
                                        float* __restrict__ Y,
                                        int ldy, int Ntot,
                                        int cid, int nc, float* SM) {
    for (int i = threadIdx.x; i < M * HD; i += 256) SM[i] = Xg[i];
    __syncthreads();
    rowdot4_body<M>(W, Y, ldy, Ntot, cid, nc, SM);
}

// ---------------- kernels ----------------

__global__ void k_reset() {
    int i = blockIdx.x * 256 + threadIdx.x;
    if (i < B * HD) {
        g_sq[i] = 0.f; g_unum[i] = 0.f; g_ctx[i] = 0.f; g_oppre[i] = 0.f;
        g_sq2[i] = 0.f; g_uslot[i] = 0.f; g_ssum[i] = 0.f;
    }
    if (i < NS * HD) g_sqs[i] = 0.f;
    if (i < B) { g_amin[i] = 0xFFFFFFFFFFFFFFFFull; g_stoplog[i] = 0.f; g_Dnum[i] = 0.f; }
}

__global__ void k_pp1(const float* __restrict__ prompt, const float* __restrict__ logic) {
    int w = threadIdx.x >> 5, lane = threadIdx.x & 31;
    int wt = blockIdx.x * 8 + w;
    if (wt < 48) {
        int b = wt / 6, hc = wt % 6;
        int h4 = hc * 32 + lane;
        const float4* p = reinterpret_cast<const float4*>(prompt + (size_t)b * LP * HD);
        float4 s = make_float4(0.f, 0.f, 0.f, 0.f);
#pragma unroll 8
        for (int l = 0; l < LP; l++) {
            float4 v = p[(size_t)l * HD4 + h4];
            s.x += v.x; s.y += v.y; s.z += v.z; s.w += v.w;
        }
        int h = h4 * 4;
        float inv = 1.f / (float)LP;
        g_cat[b * 2 * HD + h]     = s.x * inv;
        g_cat[b * 2 * HD + h + 1] = s.y * inv;
        g_cat[b * 2 * HD + h + 2] = s.z * inv;
        g_cat[b * 2 * HD + h + 3] = s.w * inv;
    } else {
        int t2 = wt - 48;
        int b = t2 / 6, hc = t2 % 6;
        int h4 = hc * 32 + lane;
        const float4* p = reinterpret_cast<const float4*>(logic + (size_t)b * LL * HD);
        float4 s = make_float4(0.f, 0.f, 0.f, 0.f);
#pragma unroll 8
        for (int l = 0; l < LL; l++) {
            float4 v = p[(size_t)l * HD4 + h4];
            s.x += v.x; s.y += v.y; s.z += v.z; s.w += v.w;
        }
        int h = h4 * 4;
        float inv = 1.f / (float)LL;
        g_cat[b * 2 * HD + HD + h]     = s.x * inv;
        g_cat[b * 2 * HD + HD + h + 1] = s.y * inv;
        g_cat[b * 2 * HD + HD + h + 2] = s.z * inv;
        g_cat[b * 2 * HD + HD + h + 3] = s.w * inv;
    }
}

__global__ void k_pp2(const float* __restrict__ w_init, const float* __restrict__ slot_q,
                      const float* __restrict__ w_slot_q, const float* __restrict__ w_gate) {
    __shared__ __align__(16) float SM[9 * 48];
    int cid = blockIdx.x, w = threadIdx.x >> 5, lane = threadIdx.x & 31;
    if (cid < 32) {
        colgemv4<8>(g_cat, 2 * HD, w_init, g_sq, 2 * HD, 32, cid, SM);
    } else if (cid < 48) {
        colgemv4<9>(slot_q, HD, w_slot_q, g_sqs, HD, 16, cid - 32, SM);
    } else {
        for (int s = w; s < NS; s += 8) {
            float p = 0.f;
            for (int k = lane; k < HD; k += 32)
                p = fmaf(slot_q[s * HD + k], w_gate[k], p);
#pragma unroll
            for (int off = 16; off; off >>= 1) p += __shfl_down_sync(0xffffffffu, p, off);
            if (lane == 0) g_gq[s] = p;
        }
    }
}

__global__ void k_pp3(const float* __restrict__ w_k) {
    __shared__ __align__(16) float SM[NS * HD];
    int cid = blockIdx.x, tid = threadIdx.x;
    if (cid < 8) {
        int b = cid;
        for (int rep = 0; rep < 3; rep++) {
            int j = rep * 256 + tid;
            g_stateA[b * HD + j] = tanhf(g_sq[b * HD + j]);
            g_sq[b * HD + j] = 0.f;
        }
    } else {
        rowdot<9>(w_k, g_sqs, g_sqk2, cid - 8, 140, SM);
    }
}

// grid 106: sq += state@w_q (32) + gh = w_hh@stOld (74)
__global__ void k_a(const float* __restrict__ st, const float* __restrict__ w_q,
                    const float* __restrict__ w_hh) {
    __shared__ __align__(16) float SM[B * HD];
    if (blockIdx.x < 32) colgemv4<8>(st, HD, w_q, g_sq, HD, 32, blockIdx.x, SM);
    else rowdot4<8>(w_hh, st, g_gh, 3 * HD, 3 * HD, blockIdx.x - 32, 74, SM);
}

// grid 96: qprime = w_k @ sq
__global__ void k_b(const float* __restrict__ w_k) {
    __shared__ __align__(16) float SM[8 * HD];
    rowdot<8>(w_k, g_sq, g_qprime, blockIdx.x, 96, SM);
}

// grid 88: fused state scores + exp + weighted prompt accum (64) + zero sq (24)
__global__ void k_cd(const float* __restrict__ prompt) {
    int cid = blockIdx.x, tid = threadIdx.x, w = tid >> 5, lane = tid & 31;
    const float scale = 0.03608439182435161f;
    if (cid < 64) {
        __shared__ __align__(16) float su[4 * HD];
        __shared__ float sD[8];
        int b = cid >> 3, ch = cid & 7;
        const float4* qp4 = reinterpret_cast<const float4*>(g_qprime + b * HD);
        float4 qv[6];
#pragma unroll
        for (int q = 0; q < 6; q++) qv[q] = qp4[q * 32 + lane];
        float4 acc[6];
#pragma unroll
        for (int q = 0; q < 6; q++) acc[q] = make_float4(0.f, 0.f, 0.f, 0.f);
        float Dw = 0.f;
        const float4* pr = reinterpret_cast<const float4*>(
            prompt + ((size_t)(b * LP + ch * 64)) * HD);
        for (int r = 0; r < 8; r++) {
            int l = w * 8 + r;
            const float4* row = pr + (size_t)l * HD4;
            float4 pv[6];
#pragma unroll
            for (int q = 0; q < 6; q++) pv[q] = row[q * 32 + lane];
            float s = 0.f;
#pragma unroll
            for (int q = 0; q < 6; q++) {
                s = fmaf(pv[q].x, qv[q].x, s); s = fmaf(pv[q].y, qv[q].y, s);
                s = fmaf(pv[q].z, qv[q].z, s); s = fmaf(pv[q].w, qv[q].w, s);
            }
#pragma unroll
            for (int off = 16; off; off >>= 1) s += __shfl_xor_sync(0xffffffffu, s, off);
            float e = expf(s * scale);
            Dw += e;
#pragma unroll
            for (int q = 0; q < 6; q++) { FMA4(acc[q], e, pv[q]); }
        }
        float4* su4 = reinterpret_cast<float4*>(su);
        if (w < 4) {
#pragma unroll
            for (int q = 0; q < 6; q++) su4[w * HD4 + q * 32 + lane] = acc[q];
        }
        if (lane == 0) sD[w] = Dw;
        __syncthreads();
        if (w >= 4) {
#pragma unroll
            for (int q = 0; q < 6; q++) {
                float4 t = su4[(w - 4) * HD4 + q * 32 + lane];
                t.x += acc[q].x; t.y += acc[q].y; t.z += acc[q].z; t.w += acc[q].w;
                su4[(w - 4) * HD4 + q * 32 + lane] = t;
            }
        }
        __syncthreads();
        for (int r = 0; r < 3; r++) {
            int j = r * 256 + tid;
            float v = su[j] + su[HD + j] + su[2 * HD + j] + su[3 * HD + j];
            atomicAdd(&g_unum[b * HD + j], v);
        }
        if (tid == 0) {
            float d = sD[0] + sD[1] + sD[2] + sD[3] + sD[4] + sD[5] + sD[6] + sD[7];
            atomicAdd(&g_Dnum[b], d);
        }
    } else {
        int i = (cid - 64) * 256 + tid;
        g_sq[i] = 0.f;
    }
}

// grid 33: ctx += (unum/D) @ w_v (32) + reset amin (1)
__global__ void k_e(const float* __restrict__ w_v) {
    __shared__ __align__(16) float SM[8 * 24];
    if (blockIdx.x < 32) {
        int cid = blockIdx.x;
        int kr = 24, k0 = cid * kr;
        for (int i = threadIdx.x; i < 8 * kr; i += 256) {
            int m = i / kr, kk = i - m * kr;
            SM[i] = g_unum[m * HD + k0 + kk] / g_Dnum[m];
        }
        __syncthreads();
        if (threadIdx.x < HD4) {
            const float4* W4 = reinterpret_cast<const float4*>(w_v);
            float4 acc[8];
#pragma unroll
            for (int m = 0; m < 8; m++) acc[m] = make_float4(0.f, 0.f, 0.f, 0.f);
#pragma unroll 4
            for (int kk = 0; kk < 24; kk++) {
                float4 wv = W4[(size_t)(k0 + kk) * HD4 + threadIdx.x];
#pragma unroll
                for (int m = 0; m < 8; m++) {
                    float s = SM[m * 24 + kk];
                    FMA4(acc[m], s, wv);
                }
            }
            int j = threadIdx.x * 4;
#pragma unroll
            for (int m = 0; m < 8; m++) {
                atomicAdd(&g_ctx[(size_t)m * HD + j],     acc[m].x);
                atomicAdd(&g_ctx[(size_t)m * HD + j + 1], acc[m].y);
                atomicAdd(&g_ctx[(size_t)m * HD + j + 2], acc[m].z);
                atomicAdd(&g_ctx[(size_t)m * HD + j + 3], acc[m].w);
            }
        }
    } else if (threadIdx.x < B) g_amin[threadIdx.x] = 0xFFFFFFFFFFFFFFFFull;
}

// grid 90: oppre (32), sq2 (32), glog (1), stop1 (1), zero unum/Dnum (24)
__global__ void k_f(const float* __restrict__ w_op_pre, const float* __restrict__ w_slot_q,
                    const float* __restrict__ w_gate, const float* __restrict__ w_stop) {
    __shared__ __align__(16) float SM[8 * 24];
    int cid = blockIdx.x, w = threadIdx.x >> 5, lane = threadIdx.x & 31;
    if (cid < 32) colgemv4<8>(g_ctx, HD, w_op_pre, g_oppre, HD, 32, cid, SM);
    else if (cid < 64) colgemv4<8>(g_ctx, HD, w_slot_q, g_sq2, HD, 32, cid - 32, SM);
    else if (cid == 64) {
        int b = w;
        float p = 0.f;
        for (int k = lane; k < HD; k += 32) p = fmaf(g_ctx[b * HD + k], w_gate[k], p);
#pragma unroll
        for (int off = 16; off; off >>= 1) p += __shfl_down_sync(0xffffffffu, p, off);
        if (lane == 0) g_glog[b] = p;
    } else if (cid == 65) {
        int b = w;
        float p = 0.f;
        for (int k = lane; k < HD; k += 32) p = fmaf(g_ctx[b * HD + k], w_stop[k], p);
#pragma unroll
        for (int off = 16; off; off >>= 1) p += __shfl_down_sync(0xffffffffu, p, off);
        if (lane == 0) g_stoplog[b] = p;
    } else {
        int i = (cid - 66) * 256 + threadIdx.x;
        g_unum[i] = 0.f;
        if (cid == 66 && threadIdx.x < B) g_Dnum[threadIdx.x] = 0.f;
    }
}

// grid 148: codebook (118) + qk2 = w_k@sq2 (30)
__global__ void k_g(const float* __restrict__ cbk, const float* __restrict__ w_k,
                    float* __restrict__ out, int t) {
    __shared__ __align__(16) float SM[B * HD];
    int cid = blockIdx.x, tid = threadIdx.x, w = tid >> 5, lane = tid & 31;
    if (cid < 118) {
        for (int i = tid; i < B * HD; i += 256) SM[i] = g_oppre[i];
        __syncthreads();
        const float4* SM4 = reinterpret_cast<const float4*>(SM);
        for (int c0 = cid * 8 + w; c0 < CBN; c0 += 2 * 944) {
            int c1 = c0 + 944;
            bool q1 = c1 < CBN;
            const float4* r0 = reinterpret_cast<const float4*>(cbk + (size_t)c0 * HD);
            const float4* r1 = reinterpret_cast<const float4*>(cbk + (size_t)(q1 ? c1 : c0) * HD);
            float a0[B], a1[B];
#pragma unroll
            for (int m = 0; m < B; m++) { a0[m] = 0.f; a1[m] = 0.f; }
#pragma unroll 2
            for (int k = lane; k < HD4; k += 32) {
                float4 x0 = r0[k], x1 = r1[k];
#pragma unroll
                for (int m = 0; m < B; m++) {
                    float4 sv = SM4[m * HD4 + k];
                    float d;
                    d = sv.x - x0.x; a0[m] = fmaf(d, d, a0[m]);
                    d = sv.y - x0.y; a0[m] = fmaf(d, d, a0[m]);
                    d = sv.z - x0.z; a0[m] = fmaf(d, d, a0[m]);
                    d = sv.w - x0.w; a0[m] = fmaf(d, d, a0[m]);
                    d = sv.x - x1.x; a1[m] = fmaf(d, d, a1[m]);
                    d = sv.y - x1.y; a1[m] = fmaf(d, d, a1[m]);
                    d = sv.z - x1.z; a1[m] = fmaf(d, d, a1[m]);
                    d = sv.w - x1.w; a1[m] = fmaf(d, d, a1[m]);
                }
            }
#pragma unroll
            for (int m = 0; m < B; m++) {
                float v0 = a0[m], v1 = a1[m];
#pragma unroll
                for (int off = 16; off; off >>= 1) {
                    v0 += __shfl_down_sync(0xffffffffu, v0, off);
                    v1 += __shfl_down_sync(0xffffffffu, v1, off);
                }
                if (lane == 0) {
                    out[OFF_OP + ((size_t)m * TT + t) * CBN + c0] = -v0;
                    unsigned long long key0 =
                        ((unsigned long long)__float_as_uint(v0) << 32) | (unsigned)c0;
                    atomicMin(&g_amin[m], key0);
                    if (q1) {
                        out[OFF_OP + ((size_t)m * TT + t) * CBN + c1] = -v1;
                        unsigned long long key1 =
                            ((unsigned long long)__float_as_uint(v1) << 32) | (unsigned)c1;
                        atomicMin(&g_amin[m], key1);
                    }
                }
            }
        }
    } else {
        rowdot4<8>(w_k, g_sq2, g_qk2, HD, HD, cid - 118, 30, SM);
    }
}

// grid 148: slot scores (128) + zero ctx/oppre/sq2 (20)
__global__ void k_h(const float* __restrict__ prompt) {
    __shared__ __align__(16) float SM[NS * HD];
    int cid = blockIdx.x, tid = threadIdx.x, w = tid >> 5, lane = tid & 31;
    const float scale = 0.03608439182435161f;
    if (cid < 128) {
        int b = cid >> 4, lc = cid & 15;
        for (int i = tid; i < NS * HD; i += 256) {
            int k = i % HD;
            SM[i] = g_qk2[b * HD + k] + g_sqk2[i];
        }
        __syncthreads();
        const float4* SM4 = reinterpret_cast<const float4*>(SM);
        int l0 = lc * 32 + w * 4;
        const float4* p0 = reinterpret_cast<const float4*>(prompt + ((size_t)(b * LP + l0)) * HD);
        float a0[NS], a1[NS], a2[NS], a3[NS];
#pragma unroll
        for (int s = 0; s < NS; s++) { a0[s] = 0.f; a1[s] = 0.f; a2[s] = 0.f; a3[s] = 0.f; }
#pragma unroll 2
        for (int k = lane; k < HD4; k += 32) {
            float4 v0 = p0[k], v1 = p0[HD4 + k], v2 = p0[2 * HD4 + k], v3 = p0[3 * HD4 + k];
#pragma unroll
            for (int s = 0; s < NS; s++) {
                float4 q = SM4[s * HD4 + k];
                a0[s] = fmaf(v0.x, q.x, a0[s]); a0[s] = fmaf(v0.y, q.y, a0[s]);
                a0[s] = fmaf(v0.z, q.z, a0[s]); a0[s] = fmaf(v0.w, q.w, a0[s]);
                a1[s] = fmaf(v1.x, q.x, a1[s]); a1[s] = fmaf(v1.y, q.y, a1[s]);
                a1[s] = fmaf(v1.z, q.z, a1[s]); a1[s] = fmaf(v1.w, q.w, a1[s]);
                a2[s] = fmaf(v2.x, q.x, a2[s]); a2[s] = fmaf(v2.y, q.y, a2[s]);
                a2[s] = fmaf(v2.z, q.z, a2[s]); a2[s] = fmaf(v2.w, q.w, a2[s]);
                a3[s] = fmaf(v3.x, q.x, a3[s]); a3[s] = fmaf(v3.y, q.y, a3[s]);
                a3[s] = fmaf(v3.z, q.z, a3[s]); a3[s] = fmaf(v3.w, q.w, a3[s]);
            }
        }
#pragma unroll
        for (int s = 0; s < NS; s++) {
            float v0 = a0[s], v1 = a1[s], v2 = a2[s], v3 = a3[s];
#pragma unroll
            for (int off = 16; off; off >>= 1) {
                v0 += __shfl_down_sync(0xffffffffu, v0, off);
                v1 += __shfl_down_sync(0xffffffffu, v1, off);
                v2 += __shfl_down_sync(0xffffffffu, v2, off);
                v3 += __shfl_down_sync(0xffffffffu, v3, off);
            }
            if (lane == 0) {
                float* dst = &g_sscore[(size_t)(b * NS + s) * LP + l0];
                dst[0] = v0 * scale;
                dst[1] = v1 * scale;
                dst[2] = v2 * scale;
                dst[3] = v3 * scale;
            }
        }
    } else {
        for (int i = (cid - 128) * 256 + tid; i < 3 * B * HD; i += 20 * 256) {
            if (i < B * HD) g_ctx[i] = 0.f;
            else if (i < 2 * B * HD) g_oppre[i - B * HD] = 0.f;
            else g_sq2[i - 2 * B * HD] = 0.f;
        }
    }
}

// grid 64: fused collapse (replicated) + weighted prompt sweep -> uslot
__global__ void k_jp(const float* __restrict__ prompt, const float* __restrict__ b_gate) {
    __shared__ float SS[NS * LP];
    __shared__ __align__(16) float su[4 * HD];
    __shared__ float sred[NS];
    __shared__ float coef[NS];
    __shared__ float wrow[64];
    int cid = blockIdx.x, tid = threadIdx.x, w = tid >> 5, lane = tid & 31;
    int b = cid >> 3, ch = cid & 7;
    for (int i = tid; i < NS * LP; i += 256) SS[i] = expf(g_sscore[(size_t)b * NS * LP + i]);
    __syncthreads();
    for (int s = w; s < NS; s += 8) {
        float p = 0.f;
        for (int l = lane; l < LP; l += 32) p += SS[s * LP + l];
#pragma unroll
        for (int off = 16; off; off >>= 1) p += __shfl_down_sync(0xffffffffu, p, off);
        if (lane == 0) sred[s] = p;
    }
    __syncthreads();
    if (tid == 0) {
        float bg = b_gate[0];
        bool any = false;
        for (int bb = 0; bb < B; bb++)
            for (int s = 0; s < NS; s++)
                if (g_glog[bb] + g_gq[s] + bg >= 0.f) any = true;
        float mask[NS], cnt = 0.f;
        if (any) {
            for (int s = 0; s < NS; s++) {
                float m = (g_glog[b] + g_gq[s] + bg >= 0.f) ? 1.f : 0.f;
                mask[s] = m; cnt += m;
            }
        } else {
            int arg = 0; float best = g_glog[b] + g_gq[0] + bg;
            for (int s = 1; s < NS; s++) {
                float v = g_glog[b] + g_gq[s] + bg;
                if (v > best) { best = v; arg = s; }
            }
            for (int s = 0; s < NS; s++) mask[s] = (s == arg) ? 1.f : 0.f;
            cnt = 1.f;
        }
        float invcnt = 1.f / fmaxf(cnt, 1.f);
        for (int s = 0; s < NS; s++) coef[s] = mask[s] * invcnt / sred[s];
    }
    __syncthreads();
    if (tid < 64) {
        int l = ch * 64 + tid;
        float ww = 0.f;
#pragma unroll
        for (int s = 0; s < NS; s++) ww = fmaf(coef[s], SS[s * LP + l], ww);
        wrow[tid] = ww;
    }
    __syncthreads();
    float4 acc[6];
#pragma unroll
    for (int q = 0; q < 6; q++) acc[q] = make_float4(0.f, 0.f, 0.f, 0.f);
    const float4* pr = reinterpret_cast<const float4*>(prompt + ((size_t)(b * LP + ch * 64)) * HD);
    for (int r = 0; r < 8; r++) {
        int l = w * 8 + r;
        float wt = wrow[l];
        const float4* row = pr + (size_t)l * HD4;
#pragma unroll
        for (int q = 0; q < 6; q++) {
            float4 pv = row[q * 32 + lane];
            FMA4(acc[q], wt, pv);
        }
    }
    float4* su4 = reinterpret_cast<float4*>(su);
    if (w < 4) {
#pragma unroll
        for (int q = 0; q < 6; q++) su4[w * HD4 + q * 32 + lane] = acc[q];
    }
    __syncthreads();
    if (w >= 4) {
#pragma unroll
        for (int q = 0; q < 6; q++) {
            float4 t = su4[(w - 4) * HD4 + q * 32 + lane];
            t.x += acc[q].x; t.y += acc[q].y; t.z += acc[q].z; t.w += acc[q].w;
            su4[(w - 4) * HD4 + q * 32 + lane] = t;
        }
    }
    __syncthreads();
    for (int r = 0; r < 3; r++) {
        int j = r * 256 + tid;
        float v = su[j] + su[HD + j] + su[2 * HD + j] + su[3 * HD + j];
        atomicAdd(&g_uslot[b * HD + j], v);
    }
}

// grid 32: ssum += uslot @ w_v
__global__ void k_k(const float* __restrict__ w_v) {
    __shared__ __align__(16) float SM[8 * 24];
    colgemv4<8>(g_uslot, HD, w_v, g_ssum, HD, 32, blockIdx.x, SM);
}

// grid 32: msum/out (8) + stop2 ; zero uslot (24)
__global__ void k_l(const float* __restrict__ cbk, const float* __restrict__ w_stop,
                    float* __restrict__ out, int t) {
    __shared__ float SRED[8];
    int cid = blockIdx.x, tid = threadIdx.x, w = tid >> 5, lane = tid & 31;
    if (cid < 8) {
        int b = cid;
        int idx = (int)(g_amin[b] & 0xFFFFFFFFull);
        float sp = 0.f;
        for (int rep = 0; rep < 3; rep++) {
            int j = rep * 256 + tid;
            float ms = tanhf(cbk[(size_t)idx * HD + j] + g_ssum[b * HD + j]);
            g_msum[b * HD + j] = ms;
            out[OFF_SUM + ((size_t)b * TT + t) * HD + j] = ms;
            sp = fmaf(ms, w_stop[HD + j], sp);
        }
#pragma unroll
        for (int off = 16; off; off >>= 1) sp += __shfl_xor_sync(0xffffffffu, sp, off);
        if (lane == 0) SRED[w] = sp;
        __syncthreads();
        if (tid == 0) {
            float tot = 0.f;
#pragma unroll
            for (int q = 0; q < 8; q++) tot += SRED[q];
            atomicAdd(&g_stoplog[b], tot);
        }
    } else {
        int i = (cid - 8) * 256 + tid;
        g_uslot[i] = 0.f;
    }
}

// grid 74: gi = w_ih @ msum
__global__ void k_m1(const float* __restrict__ w_ih) {
    __shared__ __align__(16) float SM[B * HD];
    rowdot4<8>(w_ih, g_msum, g_gi, 3 * HD, 3 * HD, blockIdx.x, 74, SM);
}

// grid 33: GRU combine (8) + SL/SP/CL (1) + zero ssum (24)
__global__ void k_m2(const float* __restrict__ stOld, float* __restrict__ stNew,
                     const float* __restrict__ b_ih, const float* __restrict__ b_hh,
                     const float* __restrict__ b_stop, float* __restrict__ out, int t) {
    int cid = blockIdx.x, tid = threadIdx.x;
    if (cid < 8) {
        int b = cid;
        for (int rep = 0; rep < 3; rep++) {
            int j = rep * 256 + tid;
            float ir = g_gi[b * 3 * HD + j] + b_ih[j];
            float iz = g_gi[b * 3 * HD + HD + j] + b_ih[HD + j];
            float in = g_gi[b * 3 * HD + 2 * HD + j] + b_ih[2 * HD + j];
            float hr = g_gh[b * 3 * HD + j] + b_hh[j];
            float hz = g_gh[b * 3 * HD + HD + j] + b_hh[HD + j];
            float hn = g_gh[b * 3 * HD + 2 * HD + j] + b_hh[2 * HD + j];
            float r = 1.f / (1.f + expf(-(ir + hr)));
            float z = 1.f / (1.f + expf(-(iz + hz)));
            float n = tanhf(in + r * hn);
            stNew[b * HD + j] = (1.f - z) * n + z * stOld[b * HD + j];
        }
    } else if (cid == 8) {
        if (tid == 0) {
            float bs = b_stop[0];
            for (int b = 0; b < B; b++) {
                float lg = g_stoplog[b] + bs;
                out[OFF_SL + b * TT + t] = lg;
                out[OFF_SP + b * TT + t] = 1.f / (1.f + expf(-lg));
                g_stoplog[b] = 0.f;
            }
            if (t == TT - 1) {
                for (int b = 0; b < B; b++) {
                    int len = TT;
                    for (int tt = 0; tt < TT; tt++)
                        if (out[OFF_SL + b * TT + tt] >= 0.f) { len = tt + 1; break; }
                    out[OFF_CL + b] = (float)len;
                }
            }
        }
    } else {
        int i = (cid - 9) * 256 + tid;
        g_ssum[i] = 0.f;
    }
}

// ---------------- host ----------------
extern "C" void kernel_launch(void* const* d_in, const int* in_sizes, int n_in,
                              void* d_out, int out_size) {
    const float* logic    = (const float*)d_in[0];
    const float* prompt   = (const float*)d_in[1];
    const float* cbk      = (const float*)d_in[2];
    const float* w_init   = (const float*)d_in[3];
    const float* w_q      = (const float*)d_in[4];
    const float* w_k      = (const float*)d_in[5];
    const float* w_v      = (const float*)d_in[6];
    const float* slot_q   = (const float*)d_in[7];
    const float* w_slot_q = (const float*)d_in[8];
    const float* w_op_pre = (const float*)d_in[9];
    const float* w_gate   = (const float*)d_in[10];
    const float* b_gate   = (const float*)d_in[11];
    const float* w_stop   = (const float*)d_in[12];
    const float* b_stop   = (const float*)d_in[13];
    const float* w_ih     = (const float*)d_in[14];
    const float* w_hh     = (const float*)d_in[15];
    const float* b_ih     = (const float*)d_in[16];
    const float* b_hh     = (const float*)d_in[17];
    float* out = (float*)d_out;

    void* p;
    float *stateA, *stateB;
    cudaGetSymbolAddress(&p, g_stateA); stateA = (float*)p;
    cudaGetSymbolAddress(&p, g_stateB); stateB = (float*)p;

    k_reset<<<28, 256>>>();
    k_pp1<<<12, 256>>>(prompt, logic);
    k_pp2<<<49, 256>>>(w_init, slot_q, w_slot_q, w_gate);
    k_pp3<<<148, 256>>>(w_k);

    for (int t = 0; t < TT; t++) {
        float* stOld = (t & 1) ? stateB : stateA;
        float* stNew = (t & 1) ? stateA : stateB;
        k_a<<<106, 256>>>(stOld, w_q, w_hh);
        k_b<<<96, 256>>>(w_k);
        k_cd<<<88, 256>>>(prompt);
        k_e<<<33, 256>>>(w_v);
        k_f<<<90, 256>>>(w_op_pre, w_slot_q, w_gate, w_stop);
        k_g<<<148, 256>>>(cbk, w_k, out, t);
        k_h<<<148, 256>>>(prompt);
        k_jp<<<64, 256>>>(prompt, b_gate);
        k_k<<<32, 256>>>(w_v);
        k_l<<<32, 256>>>(cbk, w_stop, out, t);
        k_m1<<<74, 256>>>(w_ih);
        k_m2<<<33, 256>>>(stOld, stNew, b_ih, b_hh, b_stop, out, t);
    }
}

// round 15
// speedup vs baseline: 1.0838x; 1.0157x over previous
#include <cuda_runtime.h>
#include <math.h>

#define B    8
#define HD   768
#define HD4  192
#define LP   512
#define LL   256
#define CBN  4096
#define NS   9
#define TT   4

#define OFF_SUM 0
#define OFF_SL  24576
#define OFF_SP  24608
#define OFF_OP  24640
#define OFF_CL  155712

// ---------------- device scratch ----------------
__device__ __align__(16) float g_cat[B * 2 * HD];
__device__ __align__(16) float g_stateA[B * HD];
__device__ __align__(16) float g_stateB[B * HD];
__device__ __align__(16) float g_sq[B * HD];
__device__ __align__(16) float g_qprime[B * HD];
__device__ __align__(16) float g_unum[B * HD];
__device__ float g_Dnum[B];
__device__ __align__(16) float g_ctx[B * HD];
__device__ __align__(16) float g_oppre[B * HD];
__device__ __align__(16) float g_sq2[B * HD];
__device__ __align__(16) float g_qk2[B * HD];
__device__ __align__(16) float g_sqs[NS * HD];
__device__ __align__(16) float g_sqk2[NS * HD];
__device__ float g_gq[NS];
__device__ float g_glog[B];
__device__ __align__(16) float g_sscore[B * NS * LP];
__device__ __align__(16) float g_uslot[B * HD];
__device__ __align__(16) float g_ssum[B * HD];
__device__ __align__(16) float g_msum[B * HD];
__device__ __align__(16) float g_gi[B * 3 * HD];
__device__ __align__(16) float g_gh[B * 3 * HD];
__device__ float g_stoplog[B];
__device__ unsigned long long g_amin[B];

// ---------------- side stream for graph-parallel codebook branch ----------------
static cudaStream_t g_s2;
static cudaEvent_t g_evA[TT], g_evB[TT];
namespace {
struct StreamInit {
    StreamInit() {
        cudaStreamCreate(&g_s2);
        for (int t = 0; t < TT; t++) {
            cudaEventCreateWithFlags(&g_evA[t], cudaEventDisableTiming);
            cudaEventCreateWithFlags(&g_evB[t], cudaEventDisableTiming);
        }
    }
};
StreamInit g_si;
}

// ---------------- helpers ----------------

#define FMA4(ACC, A, Bv) \
    ACC.x = fmaf(A, Bv.x, ACC.x); ACC.y = fmaf(A, Bv.y, ACC.y); \
    ACC.z = fmaf(A, Bv.z, ACC.z); ACC.w = fmaf(A, Bv.w, ACC.w);

template <int M>
__device__ __forceinline__ void colgemv4(const float* __restrict__ X, int ldx,
                                         const float* __restrict__ W,
                                         float* __restrict__ Y,
                                         int K, int nks, int cid, float* SM) {
    int kr = K / nks, k0 = cid * kr;
    for (int i = threadIdx.x; i < M * kr; i += 256) {
        int m = i / kr, kk = i - m * kr;
        SM[i] = X[(size_t)m * ldx + k0 + kk];
    }
    __syncthreads();
    if (threadIdx.x < HD4) {
        const float4* W4 = reinterpret_cast<const float4*>(W);
        float4 acc[M];
#pragma unroll
        for (int m = 0; m < M; m++) acc[m] = make_float4(0.f, 0.f, 0.f, 0.f);
#pragma unroll 4
        for (int kk = 0; kk < kr; kk++) {
            float4 wv = W4[(size_t)(k0 + kk) * HD4 + threadIdx.x];
#pragma unroll
            for (int m = 0; m < M; m++) {
                float s = SM[m * kr + kk];
                FMA4(acc[m], s, wv);
            }
        }
        int j = threadIdx.x * 4;
#pragma unroll
        for (int m = 0; m < M; m++) {
            atomicAdd(&Y[(size_t)m * HD + j],     acc[m].x);
            atomicAdd(&Y[(size_t)m * HD + j + 1], acc[m].y);
            atomicAdd(&Y[(size_t)m * HD + j + 2], acc[m].z);
            atomicAdd(&Y[(size_t)m * HD + j + 3], acc[m].w);
        }
    }
}

template <int M>
__device__ __forceinline__ void rowdot(const float* __restrict__ W,
                                       const float* __restrict__ Xg,
                                       float* __restrict__ Y,
                                       int cid, int nc, float* SM) {
    int tid = threadIdx.x, w = tid >> 5, lane = tid & 31;
    for (int i = tid; i < M * HD; i += 256) SM[i] = Xg[i];
    __syncthreads();
    const float4* SM4 = reinterpret_cast<const float4*>(SM);
    for (int n = cid * 8 + w; n < HD; n += nc * 8) {
        const float4* wr = reinterpret_cast<const float4*>(W + (size_t)n * HD);
        float acc[M];
#pragma unroll
        for (int m = 0; m < M; m++) acc[m] = 0.f;
#pragma unroll
        for (int k = lane; k < HD4; k += 32) {
            float4 wv = wr[k];
#pragma unroll
            for (int m = 0; m < M; m++) {
                float4 s = SM4[m * HD4 + k];
                acc[m] = fmaf(wv.x, s.x, acc[m]);
                acc[m] = fmaf(wv.y, s.y, acc[m]);
                acc[m] = fmaf(wv.z, s.z, acc[m]);
                acc[m] = fmaf(wv.w, s.w, acc[m]);
            }
        }
#pragma unroll
        for (int m = 0; m < M; m++) {
#pragma unroll
            for (int off = 16; off; off >>= 1)
                acc[m] += __shfl_down_sync(0xffffffffu, acc[m], off);
        }
        if (lane == 0) {
#pragma unroll
            for (int m = 0; m < M; m++) Y[(size_t)m * HD + n] = acc[m];
        }
    }
}

template <int M>
__device__ __forceinline__ void rowdot4(const float* __restrict__ W,
                                        const float* __restrict__ Xg,
                                        float* __restrict__ Y,
                                        int ldy, int Ntot,
                                        int cid, int nc, float* SM) {
    int tid = threadIdx.x, w = tid >> 5, lane = tid & 31;
    for (int i = tid; i < M * HD; i += 256) SM[i] = Xg[i];
    __syncthreads();
    const float4* SM4 = reinterpret_cast<const float4*>(SM);
    int stride = nc * 8;
    for (int n = cid * 8 + w; n < Ntot; n += 4 * stride) {
        int n1 = n + stride, n2 = n + 2 * stride, n3 = n + 3 * stride;
        bool q1 = n1 < Ntot, q2 = n2 < Ntot, q3 = n3 < Ntot;
        const float4* w0 = reinterpret_cast<const float4*>(W + (size_t)n * HD);
        const float4* w1 = reinterpret_cast<const float4*>(W + (size_t)(q1 ? n1 : n) * HD);
        const float4* w2 = reinterpret_cast<const float4*>(W + (size_t)(q2 ? n2 : n) * HD);
        const float4* w3 = reinterpret_cast<const float4*>(W + (size_t)(q3 ? n3 : n) * HD);
        float a0[M], a1[M], a2[M], a3[M];
#pragma unroll
        for (int m = 0; m < M; m++) { a0[m] = 0.f; a1[m] = 0.f; a2[m] = 0.f; a3[m] = 0.f; }
#pragma unroll 2
        for (int k = lane; k < HD4; k += 32) {
            float4 x0 = w0[k], x1 = w1[k], x2 = w2[k], x3 = w3[k];
#pragma unroll
            for (int m = 0; m < M; m++) {
                float4 s = SM4[m * HD4 + k];
                a0[m] = fmaf(x0.x, s.x, a0[m]); a0[m] = fmaf(x0.y, s.y, a0[m]);
                a0[m] = fmaf(x0.z, s.z, a0[m]); a0[m] = fmaf(x0.w, s.w, a0[m]);
                a1[m] = fmaf(x1.x, s.x, a1[m]); a1[m] = fmaf(x1.y, s.y, a1[m]);
                a1[m] = fmaf(x1.z, s.z, a1[m]); a1[m] = fmaf(x1.w, s.w, a1[m]);
                a2[m] = fmaf(x2.x, s.x, a2[m]); a2[m] = fmaf(x2.y, s.y, a2[m]);
                a2[m] = fmaf(x2.z, s.z, a2[m]); a2[m] = fmaf(x2.w, s.w, a2[m]);
                a3[m] = fmaf(x3.x, s.x, a3[m]); a3[m] = fmaf(x3.y, s.y, a3[m]);
                a3[m] = fmaf(x3.z, s.z, a3[m]); a3[m] = fmaf(x3.w, s.w, a3[m]);
            }
        }
#pragma unroll
        for (int m = 0; m < M; m++) {
            float v0 = a0[m], v1 = a1[m], v2 = a2[m], v3 = a3[m];
#pragma unroll
            for (int off = 16; off; off >>= 1) {
                v0 += __shfl_down_sync(0xffffffffu, v0, off);
                v1 += __shfl_down_sync(0xffffffffu, v1, off);
                v2 += __shfl_down_sync(0xffffffffu, v2, off);
                v3 += __shfl_down_sync(0xffffffffu, v3, off);
            }
            if (lane == 0) {
                Y[(size_t)m * ldy + n] = v0;
                if (q1) Y[(size_t)m * ldy + n1] = v1;
                if (q2) Y[(size_t)m * ldy + n2] = v2;
                if (q3) Y[(size_t)m * ldy + n3] = v3;
            }
        }
    }
}

// ---------------- kernels ----------------

__global__ void k_reset() {
    int i = blockIdx.x * 256 + threadIdx.x;
    if (i < B * HD) {
        g_sq[i] = 0.f; g_unum[i] = 0.f; g_ctx[i] = 0.f; g_oppre[i] = 0.f;
        g_sq2[i] = 0.f; g_uslot[i] = 0.f; g_ssum[i] = 0.f;
    }
    if (i < NS * HD) g_sqs[i] = 0.f;
    if (i < B) { g_amin[i] = 0xFFFFFFFFFFFFFFFFull; g_stoplog[i] = 0.f; g_Dnum[i] = 0.f; }
}

__global__ void k_pp1(const float* __restrict__ prompt, const float* __restrict__ logic) {
    int w = threadIdx.x >> 5, lane = threadIdx.x & 31;
    int wt = blockIdx.x * 8 + w;
    if (wt < 48) {
        int b = wt / 6, hc = wt % 6;
        int h4 = hc * 32 + lane;
        const float4* p = reinterpret_cast<const float4*>(prompt + (size_t)b * LP * HD);
        float4 s = make_float4(0.f, 0.f, 0.f, 0.f);
#pragma unroll 8
        for (int l = 0; l < LP; l++) {
            float4 v = p[(size_t)l * HD4 + h4];
            s.x += v.x; s.y += v.y; s.z += v.z; s.w += v.w;
        }
        int h = h4 * 4;
        float inv = 1.f / (float)LP;
        g_cat[b * 2 * HD + h]     = s.x * inv;
        g_cat[b * 2 * HD + h + 1] = s.y * inv;
        g_cat[b * 2 * HD + h + 2] = s.z * inv;
        g_cat[b * 2 * HD + h + 3] = s.w * inv;
    } else {
        int t2 = wt - 48;
        int b = t2 / 6, hc = t2 % 6;
        int h4 = hc * 32 + lane;
        const float4* p = reinterpret_cast<const float4*>(logic + (size_t)b * LL * HD);
        float4 s = make_float4(0.f, 0.f, 0.f, 0.f);
#pragma unroll 8
        for (int l = 0; l < LL; l++) {
            float4 v = p[(size_t)l * HD4 + h4];
            s.x += v.x; s.y += v.y; s.z += v.z; s.w += v.w;
        }
        int h = h4 * 4;
        float inv = 1.f / (float)LL;
        g_cat[b * 2 * HD + HD + h]     = s.x * inv;
        g_cat[b * 2 * HD + HD + h + 1] = s.y * inv;
        g_cat[b * 2 * HD + HD + h + 2] = s.z * inv;
        g_cat[b * 2 * HD + HD + h + 3] = s.w * inv;
    }
}

__global__ void k_pp2(const float* __restrict__ w_init, const float* __restrict__ slot_q,
                      const float* __restrict__ w_slot_q, const float* __restrict__ w_gate) {
    __shared__ __align__(16) float SM[9 * 48];
    int cid = blockIdx.x, w = threadIdx.x >> 5, lane = threadIdx.x & 31;
    if (cid < 32) {
        colgemv4<8>(g_cat, 2 * HD, w_init, g_sq, 2 * HD, 32, cid, SM);
    } else if (cid < 48) {
        colgemv4<9>(slot_q, HD, w_slot_q, g_sqs, HD, 16, cid - 32, SM);
    } else {
        for (int s = w; s < NS; s += 8) {
            float p = 0.f;
            for (int k = lane; k < HD; k += 32)
                p = fmaf(slot_q[s * HD + k], w_gate[k], p);
#pragma unroll
            for (int off = 16; off; off >>= 1) p += __shfl_down_sync(0xffffffffu, p, off);
            if (lane == 0) g_gq[s] = p;
        }
    }
}

__global__ void k_pp3(const float* __restrict__ w_k) {
    __shared__ __align__(16) float SM[NS * HD];
    int cid = blockIdx.x, tid = threadIdx.x;
    if (cid < 8) {
        int b = cid;
        for (int rep = 0; rep < 3; rep++) {
            int j = rep * 256 + tid;
            g_stateA[b * HD + j] = tanhf(g_sq[b * HD + j]);
            g_sq[b * HD + j] = 0.f;
        }
    } else {
        rowdot<9>(w_k, g_sqs, g_sqk2, cid - 8, 140, SM);
    }
}

// grid 106: sq += state@w_q (32) + gh = w_hh@stOld (74)
__global__ void k_a(const float* __restrict__ st, const float* __restrict__ w_q,
                    const float* __restrict__ w_hh) {
    __shared__ __align__(16) float SM[B * HD];
    if (blockIdx.x < 32) colgemv4<8>(st, HD, w_q, g_sq, HD, 32, blockIdx.x, SM);
    else rowdot4<8>(w_hh, st, g_gh, 3 * HD, 3 * HD, blockIdx.x - 32, 74, SM);
}

// grid 96: qprime = w_k @ sq
__global__ void k_b(const float* __restrict__ w_k) {
    __shared__ __align__(16) float SM[8 * HD];
    rowdot<8>(w_k, g_sq, g_qprime, blockIdx.x, 96, SM);
}

// grid 88: fused state scores + exp + weighted prompt accum (64) + zero sq (24)
__global__ void k_cd(const float* __restrict__ prompt) {
    int cid = blockIdx.x, tid = threadIdx.x, w = tid >> 5, lane = tid & 31;
    const float scale = 0.03608439182435161f;
    if (cid < 64) {
        __shared__ __align__(16) float su[4 * HD];
        __shared__ float sD[8];
        int b = cid >> 3, ch = cid & 7;
        const float4* qp4 = reinterpret_cast<const float4*>(g_qprime + b * HD);
        float4 qv[6];
#pragma unroll
        for (int q = 0; q < 6; q++) qv[q] = qp4[q * 32 + lane];
        float4 acc[6];
#pragma unroll
        for (int q = 0; q < 6; q++) acc[q] = make_float4(0.f, 0.f, 0.f, 0.f);
        float Dw = 0.f;
        const float4* pr = reinterpret_cast<const float4*>(
            prompt + ((size_t)(b * LP + ch * 64)) * HD);
        for (int r = 0; r < 8; r++) {
            int l = w * 8 + r;
            const float4* row = pr + (size_t)l * HD4;
            float4 pv[6];
#pragma unroll
            for (int q = 0; q < 6; q++) pv[q] = row[q * 32 + lane];
            float s = 0.f;
#pragma unroll
            for (int q = 0; q < 6; q++) {
                s = fmaf(pv[q].x, qv[q].x, s); s = fmaf(pv[q].y, qv[q].y, s);
                s = fmaf(pv[q].z, qv[q].z, s); s = fmaf(pv[q].w, qv[q].w, s);
            }
#pragma unroll
            for (int off = 16; off; off >>= 1) s += __shfl_xor_sync(0xffffffffu, s, off);
            float e = expf(s * scale);
            Dw += e;
#pragma unroll
            for (int q = 0; q < 6; q++) { FMA4(acc[q], e, pv[q]); }
        }
        float4* su4 = reinterpret_cast<float4*>(su);
        if (w < 4) {
#pragma unroll
            for (int q = 0; q < 6; q++) su4[w * HD4 + q * 32 + lane] = acc[q];
        }
        if (lane == 0) sD[w] = Dw;
        __syncthreads();
        if (w >= 4) {
#pragma unroll
            for (int q = 0; q < 6; q++) {
                float4 t = su4[(w - 4) * HD4 + q * 32 + lane];
                t.x += acc[q].x; t.y += acc[q].y; t.z += acc[q].z; t.w += acc[q].w;
                su4[(w - 4) * HD4 + q * 32 + lane] = t;
            }
        }
        __syncthreads();
        for (int r = 0; r < 3; r++) {
            int j = r * 256 + tid;
            float v = su[j] + su[HD + j] + su[2 * HD + j] + su[3 * HD + j];
            atomicAdd(&g_unum[b * HD + j], v);
        }
        if (tid == 0) {
            float d = sD[0] + sD[1] + sD[2] + sD[3] + sD[4] + sD[5] + sD[6] + sD[7];
            atomicAdd(&g_Dnum[b], d);
        }
    } else {
        int i = (cid - 64) * 256 + tid;
        g_sq[i] = 0.f;
    }
}

// grid 33: ctx += (unum/D) @ w_v (32) + reset amin (1)
__global__ void k_e(const float* __restrict__ w_v) {
    __shared__ __align__(16) float SM[8 * 24];
    if (blockIdx.x < 32) {
        int cid = blockIdx.x;
        int kr = 24, k0 = cid * kr;
        for (int i = threadIdx.x; i < 8 * kr; i += 256) {
            int m = i / kr, kk = i - m * kr;
            SM[i] = g_unum[m * HD + k0 + kk] / g_Dnum[m];
        }
        __syncthreads();
        if (threadIdx.x < HD4) {
            const float4* W4 = reinterpret_cast<const float4*>(w_v);
            float4 acc[8];
#pragma unroll
            for (int m = 0; m < 8; m++) acc[m] = make_float4(0.f, 0.f, 0.f, 0.f);
#pragma unroll 4
            for (int kk = 0; kk < 24; kk++) {
                float4 wv = W4[(size_t)(k0 + kk) * HD4 + threadIdx.x];
#pragma unroll
                for (int m = 0; m < 8; m++) {
                    float s = SM[m * 24 + kk];
                    FMA4(acc[m], s, wv);
                }
            }
            int j = threadIdx.x * 4;
#pragma unroll
            for (int m = 0; m < 8; m++) {
                atomicAdd(&g_ctx[(size_t)m * HD + j],     acc[m].x);
                atomicAdd(&g_ctx[(size_t)m * HD + j + 1], acc[m].y);
                atomicAdd(&g_ctx[(size_t)m * HD + j + 2], acc[m].z);
                atomicAdd(&g_ctx[(size_t)m * HD + j + 3], acc[m].w);
            }
        }
    } else if (threadIdx.x < B) g_amin[threadIdx.x] = 0xFFFFFFFFFFFFFFFFull;
}

// grid 90: oppre (32), sq2 (32), glog (1), stop1 (1), zero unum/Dnum (24)
__global__ void k_f(const float* __restrict__ w_op_pre, const float* __restrict__ w_slot_q,
                    const float* __restrict__ w_gate, const float* __restrict__ w_stop) {
    __shared__ __align__(16) float SM[8 * 24];
    int cid = blockIdx.x, w = threadIdx.x >> 5, lane = threadIdx.x & 31;
    if (cid < 32) colgemv4<8>(g_ctx, HD, w_op_pre, g_oppre, HD, 32, cid, SM);
    else if (cid < 64) colgemv4<8>(g_ctx, HD, w_slot_q, g_sq2, HD, 32, cid - 32, SM);
    else if (cid == 64) {
        int b = w;
        float p = 0.f;
        for (int k = lane; k < HD; k += 32) p = fmaf(g_ctx[b * HD + k], w_gate[k], p);
#pragma unroll
        for (int off = 16; off; off >>= 1) p += __shfl_down_sync(0xffffffffu, p, off);
        if (lane == 0) g_glog[b] = p;
    } else if (cid == 65) {
        int b = w;
        float p = 0.f;
        for (int k = lane; k < HD; k += 32) p = fmaf(g_ctx[b * HD + k], w_stop[k], p);
#pragma unroll
        for (int off = 16; off; off >>= 1) p += __shfl_down_sync(0xffffffffu, p, off);
        if (lane == 0) g_stoplog[b] = p;
    } else {
        int i = (cid - 66) * 256 + threadIdx.x;
        g_unum[i] = 0.f;
        if (cid == 66 && threadIdx.x < B) g_Dnum[threadIdx.x] = 0.f;
    }
}

// grid 118 (stream s2): codebook distances + argmin
__global__ void k_gcb(const float* __restrict__ cbk, float* __restrict__ out, int t) {
    __shared__ __align__(16) float SM[B * HD];
    int cid = blockIdx.x, tid = threadIdx.x, w = tid >> 5, lane = tid & 31;
    for (int i = tid; i < B * HD; i += 256) SM[i] = g_oppre[i];
    __syncthreads();
    const float4* SM4 = reinterpret_cast<const float4*>(SM);
    for (int c0 = cid * 8 + w; c0 < CBN; c0 += 2 * 944) {
        int c1 = c0 + 944;
        bool q1 = c1 < CBN;
        const float4* r0 = reinterpret_cast<const float4*>(cbk + (size_t)c0 * HD);
        const float4* r1 = reinterpret_cast<const float4*>(cbk + (size_t)(q1 ? c1 : c0) * HD);
        float a0[B], a1[B];
#pragma unroll
        for (int m = 0; m < B; m++) { a0[m] = 0.f; a1[m] = 0.f; }
#pragma unroll 2
        for (int k = lane; k < HD4; k += 32) {
            float4 x0 = r0[k], x1 = r1[k];
#pragma unroll
            for (int m = 0; m < B; m++) {
                float4 sv = SM4[m * HD4 + k];
                float d;
                d = sv.x - x0.x; a0[m] = fmaf(d, d, a0[m]);
                d = sv.y - x0.y; a0[m] = fmaf(d, d, a0[m]);
                d = sv.z - x0.z; a0[m] = fmaf(d, d, a0[m]);
                d = sv.w - x0.w; a0[m] = fmaf(d, d, a0[m]);
                d = sv.x - x1.x; a1[m] = fmaf(d, d, a1[m]);
                d = sv.y - x1.y; a1[m] = fmaf(d, d, a1[m]);
                d = sv.z - x1.z; a1[m] = fmaf(d, d, a1[m]);
                d = sv.w - x1.w; a1[m] = fmaf(d, d, a1[m]);
            }
        }
#pragma unroll
        for (int m = 0; m < B; m++) {
            float v0 = a0[m], v1 = a1[m];
#pragma unroll
            for (int off = 16; off; off >>= 1) {
                v0 += __shfl_down_sync(0xffffffffu, v0, off);
                v1 += __shfl_down_sync(0xffffffffu, v1, off);
            }
            if (lane == 0) {
                out[OFF_OP + ((size_t)m * TT + t) * CBN + c0] = -v0;
                unsigned long long key0 =
                    ((unsigned long long)__float_as_uint(v0) << 32) | (unsigned)c0;
                atomicMin(&g_amin[m], key0);
                if (q1) {
                    out[OFF_OP + ((size_t)m * TT + t) * CBN + c1] = -v1;
                    unsigned long long key1 =
                        ((unsigned long long)__float_as_uint(v1) << 32) | (unsigned)c1;
                    atomicMin(&g_amin[m], key1);
                }
            }
        }
    }
}

// grid 48: qk2 = w_k @ sq2
__global__ void k_g2(const float* __restrict__ w_k) {
    __shared__ __align__(16) float SM[B * HD];
    rowdot4<8>(w_k, g_sq2, g_qk2, HD, HD, blockIdx.x, 48, SM);
}

// grid 128: slot scores
__global__ void k_h(const float* __restrict__ prompt) {
    __shared__ __align__(16) float SM[NS * HD];
    int cid = blockIdx.x, tid = threadIdx.x, w = tid >> 5, lane = tid & 31;
    const float scale = 0.03608439182435161f;
    int b = cid >> 4, lc = cid & 15;
    for (int i = tid; i < NS * HD; i += 256) {
        int k = i % HD;
        SM[i] = g_qk2[b * HD + k] + g_sqk2[i];
    }
    __syncthreads();
    const float4* SM4 = reinterpret_cast<const float4*>(SM);
    int l0 = lc * 32 + w * 4;
    const float4* p0 = reinterpret_cast<const float4*>(prompt + ((size_t)(b * LP + l0)) * HD);
    float a0[NS], a1[NS], a2[NS], a3[NS];
#pragma unroll
    for (int s = 0; s < NS; s++) { a0[s] = 0.f; a1[s] = 0.f; a2[s] = 0.f; a3[s] = 0.f; }
#pragma unroll 2
    for (int k = lane; k < HD4; k += 32) {
        float4 v0 = p0[k], v1 = p0[HD4 + k], v2 = p0[2 * HD4 + k], v3 = p0[3 * HD4 + k];
#pragma unroll
        for (int s = 0; s < NS; s++) {
            float4 q = SM4[s * HD4 + k];
            a0[s] = fmaf(v0.x, q.x, a0[s]); a0[s] = fmaf(v0.y, q.y, a0[s]);
            a0[s] = fmaf(v0.z, q.z, a0[s]); a0[s] = fmaf(v0.w, q.w, a0[s]);
            a1[s] = fmaf(v1.x, q.x, a1[s]); a1[s] = fmaf(v1.y, q.y, a1[s]);
            a1[s] = fmaf(v1.z, q.z, a1[s]); a1[s] = fmaf(v1.w, q.w, a1[s]);
            a2[s] = fmaf(v2.x, q.x, a2[s]); a2[s] = fmaf(v2.y, q.y, a2[s]);
            a2[s] = fmaf(v2.z, q.z, a2[s]); a2[s] = fmaf(v2.w, q.w, a2[s]);
            a3[s] = fmaf(v3.x, q.x, a3[s]); a3[s] = fmaf(v3.y, q.y, a3[s]);
            a3[s] = fmaf(v3.z, q.z, a3[s]); a3[s] = fmaf(v3.w, q.w, a3[s]);
        }
    }
#pragma unroll
    for (int s = 0; s < NS; s++) {
        float v0 = a0[s], v1 = a1[s], v2 = a2[s], v3 = a3[s];
#pragma unroll
        for (int off = 16; off; off >>= 1) {
            v0 += __shfl_down_sync(0xffffffffu, v0, off);
            v1 += __shfl_down_sync(0xffffffffu, v1, off);
            v2 += __shfl_down_sync(0xffffffffu, v2, off);
            v3 += __shfl_down_sync(0xffffffffu, v3, off);
        }
        if (lane == 0) {
            float* dst = &g_sscore[(size_t)(b * NS + s) * LP + l0];
            dst[0] = v0 * scale;
            dst[1] = v1 * scale;
            dst[2] = v2 * scale;
            dst[3] = v3 * scale;
        }
    }
}

// grid 64: fused collapse (replicated) + weighted prompt sweep -> uslot
__global__ void k_jp(const float* __restrict__ prompt, const float* __restrict__ b_gate) {
    __shared__ float SS[NS * LP];
    __shared__ __align__(16) float su[4 * HD];
    __shared__ float sred[NS];
    __shared__ float coef[NS];
    __shared__ float wrow[64];
    int cid = blockIdx.x, tid = threadIdx.x, w = tid >> 5, lane = tid & 31;
    int b = cid >> 3, ch = cid & 7;
    for (int i = tid; i < NS * LP; i += 256) SS[i] = expf(g_sscore[(size_t)b * NS * LP + i]);
    __syncthreads();
    for (int s = w; s < NS; s += 8) {
        float p = 0.f;
        for (int l = lane; l < LP; l += 32) p += SS[s * LP + l];
#pragma unroll
        for (int off = 16; off; off >>= 1) p += __shfl_down_sync(0xffffffffu, p, off);
        if (lane == 0) sred[s] = p;
    }
    __syncthreads();
    if (tid == 0) {
        float bg = b_gate[0];
        bool any = false;
        for (int bb = 0; bb < B; bb++)
            for (int s = 0; s < NS; s++)
                if (g_glog[bb] + g_gq[s] + bg >= 0.f) any = true;
        float mask[NS], cnt = 0.f;
        if (any) {
            for (int s = 0; s < NS; s++) {
                float m = (g_glog[b] + g_gq[s] + bg >= 0.f) ? 1.f : 0.f;
                mask[s] = m; cnt += m;
            }
        } else {
            int arg = 0; float best = g_glog[b] + g_gq[0] + bg;
            for (int s = 1; s < NS; s++) {
                float v = g_glog[b] + g_gq[s] + bg;
                if (v > best) { best = v; arg = s; }
            }
            for (int s = 0; s < NS; s++) mask[s] = (s == arg) ? 1.f : 0.f;
            cnt = 1.f;
        }
        float invcnt = 1.f / fmaxf(cnt, 1.f);
        for (int s = 0; s < NS; s++) coef[s] = mask[s] * invcnt / sred[s];
    }
    __syncthreads();
    if (tid < 64) {
        int l = ch * 64 + tid;
        float ww = 0.f;
#pragma unroll
        for (int s = 0; s < NS; s++) ww = fmaf(coef[s], SS[s * LP + l], ww);
        wrow[tid] = ww;
    }
    __syncthreads();
    float4 acc[6];
#pragma unroll
    for (int q = 0; q < 6; q++) acc[q] = make_float4(0.f, 0.f, 0.f, 0.f);
    const float4* pr = reinterpret_cast<const float4*>(prompt + ((size_t)(b * LP + ch * 64)) * HD);
    for (int r = 0; r < 8; r++) {
        int l = w * 8 + r;
        float wt = wrow[l];
        const float4* row = pr + (size_t)l * HD4;
#pragma unroll
        for (int q = 0; q < 6; q++) {
            float4 pv = row[q * 32 + lane];
            FMA4(acc[q], wt, pv);
        }
    }
    float4* su4 = reinterpret_cast<float4*>(su);
    if (w < 4) {
#pragma unroll
        for (int q = 0; q < 6; q++) su4[w * HD4 + q * 32 + lane] = acc[q];
    }
    __syncthreads();
    if (w >= 4) {
#pragma unroll
        for (int q = 0; q < 6; q++) {
            float4 t = su4[(w - 4) * HD4 + q * 32 + lane];
            t.x += acc[q].x; t.y += acc[q].y; t.z += acc[q].z; t.w += acc[q].w;
            su4[(w - 4) * HD4 + q * 32 + lane] = t;
        }
    }
    __syncthreads();
    for (int r = 0; r < 3; r++) {
        int j = r * 256 + tid;
        float v = su[j] + su[HD + j] + su[2 * HD + j] + su[3 * HD + j];
        atomicAdd(&g_uslot[b * HD + j], v);
    }
}

// grid 32: ssum += uslot @ w_v
__global__ void k_k(const float* __restrict__ w_v) {
    __shared__ __align__(16) float SM[8 * 24];
    colgemv4<8>(g_uslot, HD, w_v, g_ssum, HD, 32, blockIdx.x, SM);
}

// grid 32: msum/out (8) + stop2 ; zero uslot (24)
__global__ void k_l(const float* __restrict__ cbk, const float* __restrict__ w_stop,
                    float* __restrict__ out, int t) {
    __shared__ float SRED[8];
    int cid = blockIdx.x, tid = threadIdx.x, w = tid >> 5, lane = tid & 31;
    if (cid < 8) {
        int b = cid;
        int idx = (int)(g_amin[b] & 0xFFFFFFFFull);
        float sp = 0.f;
        for (int rep = 0; rep < 3; rep++) {
            int j = rep * 256 + tid;
            float ms = tanhf(cbk[(size_t)idx * HD + j] + g_ssum[b * HD + j]);
            g_msum[b * HD + j] = ms;
            out[OFF_SUM + ((size_t)b * TT + t) * HD + j] = ms;
            sp = fmaf(ms, w_stop[HD + j], sp);
        }
#pragma unroll
        for (int off = 16; off; off >>= 1) sp += __shfl_xor_sync(0xffffffffu, sp, off);
        if (lane == 0) SRED[w] = sp;
        __syncthreads();
        if (tid == 0) {
            float tot = 0.f;
#pragma unroll
            for (int q = 0; q < 8; q++) tot += SRED[q];
            atomicAdd(&g_stoplog[b], tot);
        }
    } else {
        int i = (cid - 8) * 256 + tid;
        g_uslot[i] = 0.f;
    }
}

// grid 100: gi = w_ih @ msum (74) + zero ctx/oppre/sq2 (26)
__global__ void k_m1(const float* __restrict__ w_ih) {
    __shared__ __align__(16) float SM[B * HD];
    int cid = blockIdx.x, tid = threadIdx.x;
    if (cid < 74) {
        rowdot4<8>(w_ih, g_msum, g_gi, 3 * HD, 3 * HD, cid, 74, SM);
    } else {
        for (int i = (cid - 74) * 256 + tid; i < 3 * B * HD; i += 26 * 256) {
            if (i < B * HD) g_ctx[i] = 0.f;
            else if (i < 2 * B * HD) g_oppre[i - B * HD] = 0.f;
            else g_sq2[i - 2 * B * HD] = 0.f;
        }
    }
}

// grid 33: GRU combine (8) + SL/SP/CL (1) + zero ssum (24)
__global__ void k_m2(const float* __restrict__ stOld, float* __restrict__ stNew,
                     const float* __restrict__ b_ih, const float* __restrict__ b_hh,
                     const float* __restrict__ b_stop, float* __restrict__ out, int t) {
    int cid = blockIdx.x, tid = threadIdx.x;
    if (cid < 8) {
        int b = cid;
        for (int rep = 0; rep < 3; rep++) {
            int j = rep * 256 + tid;
            float ir = g_gi[b * 3 * HD + j] + b_ih[j];
            float iz = g_gi[b * 3 * HD + HD + j] + b_ih[HD + j];
            float in = g_gi[b * 3 * HD + 2 * HD + j] + b_ih[2 * HD + j];
            float hr = g_gh[b * 3 * HD + j] + b_hh[j];
            float hz = g_gh[b * 3 * HD + HD + j] + b_hh[HD + j];
            float hn = g_gh[b * 3 * HD + 2 * HD + j] + b_hh[2 * HD + j];
            float r = 1.f / (1.f + expf(-(ir + hr)));
            float z = 1.f / (1.f + expf(-(iz + hz)));
            float n = tanhf(in + r * hn);
            stNew[b * HD + j] = (1.f - z) * n + z * stOld[b * HD + j];
        }
    } else if (cid == 8) {
        if (tid == 0) {
            float bs = b_stop[0];
            for (int b = 0; b < B; b++) {
                float lg = g_stoplog[b] + bs;
                out[OFF_SL + b * TT + t] = lg;
                out[OFF_SP + b * TT + t] = 1.f / (1.f + expf(-lg));
                g_stoplog[b] = 0.f;
            }
            if (t == TT - 1) {
                for (int b = 0; b < B; b++) {
                    int len = TT;
                    for (int tt = 0; tt < TT; tt++)
                        if (out[OFF_SL + b * TT + tt] >= 0.f) { len = tt + 1; break; }
                    out[OFF_CL + b] = (float)len;
                }
            }
        }
    } else {
        int i = (cid - 9) * 256 + tid;
        g_ssum[i] = 0.f;
    }
}

// ---------------- host ----------------
extern "C" void kernel_launch(void* const* d_in, const int* in_sizes, int n_in,
                              void* d_out, int out_size) {
    const float* logic    = (const float*)d_in[0];
    const float* prompt   = (const float*)d_in[1];
    const float* cbk      = (const float*)d_in[2];
    const float* w_init   = (const float*)d_in[3];
    const float* w_q      = (const float*)d_in[4];
    const float* w_k      = (const float*)d_in[5];
    const float* w_v      = (const float*)d_in[6];
    const float* slot_q   = (const float*)d_in[7];
    const float* w_slot_q = (const float*)d_in[8];
    const float* w_op_pre = (const float*)d_in[9];
    const float* w_gate   = (const float*)d_in[10];
    const float* b_gate   = (const float*)d_in[11];
    const float* w_stop   = (const float*)d_in[12];
    const float* b_stop   = (const float*)d_in[13];
    const float* w_ih     = (const float*)d_in[14];
    const float* w_hh     = (const float*)d_in[15];
    const float* b_ih     = (const float*)d_in[16];
    const float* b_hh     = (const float*)d_in[17];
    float* out = (float*)d_out;

    void* p;
    float *stateA, *stateB;
    cudaGetSymbolAddress(&p, g_stateA); stateA = (float*)p;
    cudaGetSymbolAddress(&p, g_stateB); stateB = (float*)p;

    k_reset<<<28, 256>>>();
    k_pp1<<<12, 256>>>(prompt, logic);
    k_pp2<<<49, 256>>>(w_init, slot_q, w_slot_q, w_gate);
    k_pp3<<<148, 256>>>(w_k);

    for (int t = 0; t < TT; t++) {
        float* stOld = (t & 1) ? stateB : stateA;
        float* stNew = (t & 1) ? stateA : stateB;
        k_a<<<106, 256>>>(stOld, w_q, w_hh);
        k_b<<<96, 256>>>(w_k);
        k_cd<<<88, 256>>>(prompt);
        k_e<<<33, 256>>>(w_v);
        k_f<<<90, 256>>>(w_op_pre, w_slot_q, w_gate, w_stop);
        // fork: codebook branch on s2, slot branch on main stream
        cudaEventRecord(g_evA[t], 0);
        cudaStreamWaitEvent(g_s2, g_evA[t], 0);
        k_gcb<<<118, 256, 0, g_s2>>>(cbk, out, t);
        k_g2<<<48, 256>>>(w_k);
        k_h<<<128, 256>>>(prompt);
        k_jp<<<64, 256>>>(prompt, b_gate);
        k_k<<<32, 256>>>(w_v);
        // join
        cudaEventRecord(g_evB[t], g_s2);
        cudaStreamWaitEvent(0, g_evB[t], 0);
        k_l<<<32, 256>>>(cbk, w_stop, out, t);
        k_m1<<<100, 256>>>(w_ih);
        k_m2<<<33, 256>>>(stOld, stNew, b_ih, b_hh, b_stop, out, t);
    }
}